// round 5
// baseline (speedup 1.0000x reference)
#include <cuda_runtime.h>
#include <cuda_bf16.h>
#include <cstdint>

#define S_LEN 1024
#define BDIM  2
#define HQ    4096
#define NKV   8
#define GSZ   8
#define NH    64
#define DH    64
#define MROWS (BDIM * S_LEN)   // 2048

// ---------------- scratch (device globals; no allocs allowed) ----------------
__device__ float g_q [MROWS * HQ];        // 33.5 MB
__device__ float g_k [MROWS * NKV * DH];  // 4 MB
__device__ float g_v [MROWS * NKV * DH];  // 4 MB
__device__ float g_ao[MROWS * HQ];        // 33.5 MB

// ---------------- GEMM: C[m,n] = sum_k A[m,k] * W[n,k] ----------------
#define BM 128
#define BN 128
#define BK 16
#define LDT (BM + 4)   // 132: 2-way max conflict on transpose-store, aligned rows

__device__ __forceinline__ void gemm_nt_body(
    const float* __restrict__ A, const float* __restrict__ W, float* __restrict__ C,
    int K, int ldc, int m0, int n0,
    float (*As)[LDT], float (*Bs)[LDT])
{
    const int tid = threadIdx.x;
    const int tx = tid & 15;         // 0..15 -> col frag
    const int ty = tid >> 4;         // 0..15 -> row frag

    float acc[8][8];
#pragma unroll
    for (int i = 0; i < 8; i++)
#pragma unroll
        for (int j = 0; j < 8; j++) acc[i][j] = 0.f;

    for (int k0 = 0; k0 < K; k0 += BK) {
#pragma unroll
        for (int r = 0; r < 2; r++) {
            int slot = tid + r * 256;          // 0..511
            int row  = slot >> 2;              // 0..127
            int c4   = (slot & 3) * 4;         // 0,4,8,12
            float4 av = *(const float4*)&A[(size_t)(m0 + row) * K + k0 + c4];
            As[c4 + 0][row] = av.x; As[c4 + 1][row] = av.y;
            As[c4 + 2][row] = av.z; As[c4 + 3][row] = av.w;
            float4 bv = *(const float4*)&W[(size_t)(n0 + row) * K + k0 + c4];
            Bs[c4 + 0][row] = bv.x; Bs[c4 + 1][row] = bv.y;
            Bs[c4 + 2][row] = bv.z; Bs[c4 + 3][row] = bv.w;
        }
        __syncthreads();
#pragma unroll
        for (int kk = 0; kk < BK; kk++) {
            float a[8], b[8];
            float4 a0 = *(const float4*)&As[kk][ty * 8];
            float4 a1 = *(const float4*)&As[kk][ty * 8 + 4];
            a[0]=a0.x; a[1]=a0.y; a[2]=a0.z; a[3]=a0.w;
            a[4]=a1.x; a[5]=a1.y; a[6]=a1.z; a[7]=a1.w;
            float4 b0 = *(const float4*)&Bs[kk][tx * 8];
            float4 b1 = *(const float4*)&Bs[kk][tx * 8 + 4];
            b[0]=b0.x; b[1]=b0.y; b[2]=b0.z; b[3]=b0.w;
            b[4]=b1.x; b[5]=b1.y; b[6]=b1.z; b[7]=b1.w;
#pragma unroll
            for (int i = 0; i < 8; i++)
#pragma unroll
                for (int j = 0; j < 8; j++)
                    acc[i][j] = fmaf(a[i], b[j], acc[i][j]);
        }
        __syncthreads();
    }

#pragma unroll
    for (int i = 0; i < 8; i++) {
        float* cp = &C[(size_t)(m0 + ty * 8 + i) * ldc + n0 + tx * 8];
        float4 c0 = make_float4(acc[i][0], acc[i][1], acc[i][2], acc[i][3]);
        float4 c1 = make_float4(acc[i][4], acc[i][5], acc[i][6], acc[i][7]);
        *(float4*)cp       = c0;
        *(float4*)(cp + 4) = c1;
    }
}

__global__ void __launch_bounds__(256) gemm_nt_kernel(
    const float* __restrict__ A, const float* __restrict__ W, float* __restrict__ C, int K, int N)
{
    __shared__ float As[BK][LDT];
    __shared__ float Bs[BK][LDT];
    gemm_nt_body(A, W, C, K, N, blockIdx.y * BM, blockIdx.x * BN, As, Bs);
}

// Fused K + V projection: grid.x = 8 tiles; 0..3 -> K, 4..7 -> V (N=512 each)
__global__ void __launch_bounds__(256) gemm_kv_kernel(
    const float* __restrict__ A, const float* __restrict__ Wk, const float* __restrict__ Wv)
{
    __shared__ float As[BK][LDT];
    __shared__ float Bs[BK][LDT];
    const float* W;
    float* C;
    int n0;
    if (blockIdx.x < 4) { W = Wk; C = g_k; n0 = blockIdx.x * BN; }
    else                { W = Wv; C = g_v; n0 = (blockIdx.x - 4) * BN; }
    gemm_nt_body(A, W, C, HQ, NKV * DH, blockIdx.y * BM, n0, As, Bs);
}

// ---------------- RoPE (in-place, pair (d, d+32)) ----------------
__global__ void rope_kernel(float* __restrict__ p, const float* __restrict__ cosb,
                            const float* __restrict__ sinb, int nheads)
{
    int idx = blockIdx.x * blockDim.x + threadIdx.x;
    int total = MROWS * nheads * (DH / 2);
    if (idx >= total) return;
    int d   = idx & 31;
    int h   = (idx >> 5) % nheads;
    int bs  = idx / (nheads * 32);
    int s   = bs & (S_LEN - 1);
    size_t base = (size_t)bs * nheads * DH + h * DH;
    float x1 = p[base + d];
    float x2 = p[base + d + 32];
    float c1 = cosb[s * DH + d],      s1 = sinb[s * DH + d];
    float c2 = cosb[s * DH + d + 32], s2 = sinb[s * DH + d + 32];
    p[base + d]      = x1 * c1 - x2 * s1;
    p[base + d + 32] = x2 * c2 + x1 * s2;
}

// ---------------- Flash attention (causal, GQA) ----------------
// grid: (S/64, NH, B), block 256. Each lane group of 4 owns one q row (16 dims each).
__global__ void __launch_bounds__(256) attn_kernel(
    const float* __restrict__ q, const float* __restrict__ k,
    const float* __restrict__ v, float* __restrict__ o)
{
    const int b   = blockIdx.z;
    const int h   = blockIdx.y;
    const int kvh = h >> 3;            // h / G
    const int q0  = blockIdx.x * 64;
    const int tid = threadIdx.x;
    const int i   = tid >> 2;          // q row in tile (0..63)
    const int dsl = (tid & 3) * 16;    // dim slice start

    __shared__ float ks[64][68];
    __shared__ float vs[64][68];

    // q row slice -> registers
    float qreg[16];
    {
        const float* qp = q + (size_t)(b * S_LEN + q0 + i) * HQ + h * DH + dsl;
#pragma unroll
        for (int u = 0; u < 16; u += 4) {
            float4 t4 = *(const float4*)(qp + u);
            qreg[u] = t4.x; qreg[u + 1] = t4.y; qreg[u + 2] = t4.z; qreg[u + 3] = t4.w;
        }
    }

    float oacc[16];
#pragma unroll
    for (int u = 0; u < 16; u++) oacc[u] = 0.f;
    float mrow = -1e30f, lrow = 0.f;

    const float* kbase = k + (size_t)b * S_LEN * (NKV * DH) + kvh * DH;
    const float* vbase = v + (size_t)b * S_LEN * (NKV * DH) + kvh * DH;

    for (int j0 = 0; j0 <= q0; j0 += 64) {
        // load 64x64 K and V tiles
#pragma unroll
        for (int r = 0; r < 4; r++) {
            int slot = tid + 256 * r;          // 0..1023
            int row  = slot >> 4;              // 0..63
            int c4   = (slot & 15) * 4;        // 0..60
            *(float4*)&ks[row][c4] = *(const float4*)&kbase[(size_t)(j0 + row) * (NKV * DH) + c4];
            *(float4*)&vs[row][c4] = *(const float4*)&vbase[(size_t)(j0 + row) * (NKV * DH) + c4];
        }
        __syncthreads();

        const bool diag = (j0 == q0);
        for (int jc = 0; jc < 64; jc += 16) {
            float sc[16];
#pragma unroll
            for (int jj = 0; jj < 16; jj++) {
                int j = jc + jj;
                float dot = 0.f;
#pragma unroll
                for (int u = 0; u < 16; u += 4) {
                    float4 kv4 = *(const float4*)&ks[j][dsl + u];
                    dot = fmaf(qreg[u],     kv4.x, dot);
                    dot = fmaf(qreg[u + 1], kv4.y, dot);
                    dot = fmaf(qreg[u + 2], kv4.z, dot);
                    dot = fmaf(qreg[u + 3], kv4.w, dot);
                }
                dot += __shfl_xor_sync(0xffffffffu, dot, 1);
                dot += __shfl_xor_sync(0xffffffffu, dot, 2);
                dot *= 0.125f;                         // 1/sqrt(64)
                if (diag && (j0 + j > q0 + i)) dot = -1e30f;
                sc[jj] = dot;
            }
            float mc = sc[0];
#pragma unroll
            for (int jj = 1; jj < 16; jj++) mc = fmaxf(mc, sc[jj]);
            float mnew  = fmaxf(mrow, mc);
            float scale = __expf(mrow - mnew);
            mrow = mnew;
            lrow *= scale;
#pragma unroll
            for (int u = 0; u < 16; u++) oacc[u] *= scale;

            float psum = 0.f;
#pragma unroll
            for (int jj = 0; jj < 16; jj++) {
                float p = (sc[jj] <= -1e29f) ? 0.f : __expf(sc[jj] - mnew);
                psum += p;
                int j = jc + jj;
#pragma unroll
                for (int u = 0; u < 16; u += 4) {
                    float4 vv = *(const float4*)&vs[j][dsl + u];
                    oacc[u]     = fmaf(p, vv.x, oacc[u]);
                    oacc[u + 1] = fmaf(p, vv.y, oacc[u + 1]);
                    oacc[u + 2] = fmaf(p, vv.z, oacc[u + 2]);
                    oacc[u + 3] = fmaf(p, vv.w, oacc[u + 3]);
                }
            }
            lrow += psum;
        }
        __syncthreads();
    }

    float inv = 1.f / lrow;
    float* op = o + (size_t)(b * S_LEN + q0 + i) * HQ + h * DH + dsl;
#pragma unroll
    for (int u = 0; u < 16; u += 4) {
        float4 r = make_float4(oacc[u] * inv, oacc[u + 1] * inv,
                               oacc[u + 2] * inv, oacc[u + 3] * inv);
        *(float4*)(op + u) = r;
    }
}

// ---------------- launch ----------------
extern "C" void kernel_launch(void* const* d_in, const int* in_sizes, int n_in,
                              void* d_out, int out_size)
{
    const float* hs   = (const float*)d_in[0];
    // d_in[1] alibi, d_in[2] attention_mask: zeros, unused by reference
    const float* cosb = (const float*)d_in[3];
    const float* sinb = (const float*)d_in[4];
    const float* wq   = (const float*)d_in[5];
    const float* wk   = (const float*)d_in[6];
    const float* wv   = (const float*)d_in[7];
    const float* wd   = (const float*)d_in[8];
    float* out = (float*)d_out;

    float *pq, *pk, *pv, *pao;
    cudaGetSymbolAddress((void**)&pq,  g_q);
    cudaGetSymbolAddress((void**)&pk,  g_k);
    cudaGetSymbolAddress((void**)&pv,  g_v);
    cudaGetSymbolAddress((void**)&pao, g_ao);

    // 1. Q projection: (2048 x 4096) = hs @ wq^T
    gemm_nt_kernel<<<dim3(HQ / BN, MROWS / BM), 256>>>(hs, wq, pq, HQ, HQ);
    // 2. K+V projection fused
    gemm_kv_kernel<<<dim3(8, MROWS / BM), 256>>>(hs, wk, wv);
    // 3. RoPE on q and k
    {
        int tq = MROWS * NH * (DH / 2);
        rope_kernel<<<(tq + 255) / 256, 256>>>(pq, cosb, sinb, NH);
        int tk = MROWS * NKV * (DH / 2);
        rope_kernel<<<(tk + 255) / 256, 256>>>(pk, cosb, sinb, NKV);
    }
    // 4. causal flash attention
    attn_kernel<<<dim3(S_LEN / 64, NH, BDIM), 256>>>(pq, pk, pv, pao);
    // 5. output projection
    gemm_nt_kernel<<<dim3(HQ / BN, MROWS / BM), 256>>>(pao, wd, out, HQ, HQ);
}

// round 7
// speedup vs baseline: 1.4022x; 1.4022x over previous
#include <cuda_runtime.h>
#include <cuda_bf16.h>
#include <cstdint>

#define S_LEN 1024
#define BDIM  2
#define HQ    4096
#define NKV   8
#define NH    64
#define DH    64
#define MROWS (BDIM * S_LEN)   // 2048
#define KVDIM (NKV * DH)       // 512

// ---------------- scratch (device globals; no allocs allowed) ----------------
__device__ float g_q [MROWS * HQ];
__device__ float g_k [MROWS * KVDIM];
__device__ float g_v [MROWS * KVDIM];
__device__ __nv_bfloat16 g_hsH[MROWS * HQ], g_hsL[MROWS * HQ];
__device__ __nv_bfloat16 g_aoH[MROWS * HQ], g_aoL[MROWS * HQ];
__device__ __nv_bfloat16 g_wqH[HQ * HQ],    g_wqL[HQ * HQ];
__device__ __nv_bfloat16 g_wdH[HQ * HQ],    g_wdL[HQ * HQ];
__device__ __nv_bfloat16 g_wkH[KVDIM * HQ], g_wkL[KVDIM * HQ];
__device__ __nv_bfloat16 g_wvH[KVDIM * HQ], g_wvL[KVDIM * HQ];

// ---------------- fp32 -> (hi, lo) bf16 split ----------------
__global__ void __launch_bounds__(256) split_kernel(
    const float* __restrict__ x, __nv_bfloat16* __restrict__ hi,
    __nv_bfloat16* __restrict__ lo, int n4)
{
    int i = blockIdx.x * blockDim.x + threadIdx.x;
    if (i >= n4) return;
    float4 v = ((const float4*)x)[i];
    __nv_bfloat16 h0 = __float2bfloat16(v.x);
    __nv_bfloat16 h1 = __float2bfloat16(v.y);
    __nv_bfloat16 h2 = __float2bfloat16(v.z);
    __nv_bfloat16 h3 = __float2bfloat16(v.w);
    __nv_bfloat16 l0 = __float2bfloat16(v.x - __bfloat162float(h0));
    __nv_bfloat16 l1 = __float2bfloat16(v.y - __bfloat162float(h1));
    __nv_bfloat16 l2 = __float2bfloat16(v.z - __bfloat162float(h2));
    __nv_bfloat16 l3 = __float2bfloat16(v.w - __bfloat162float(h3));
    __nv_bfloat162* hp = (__nv_bfloat162*)hi + (size_t)i * 2;
    __nv_bfloat162* lp = (__nv_bfloat162*)lo + (size_t)i * 2;
    hp[0] = __halves2bfloat162(h0, h1);
    hp[1] = __halves2bfloat162(h2, h3);
    lp[0] = __halves2bfloat162(l0, l1);
    lp[1] = __halves2bfloat162(l2, l3);
}

// ---------------- bf16 split-GEMM: C[m,n] = sum_k A[m,k]*W[n,k] ----------------
// C = Ah*Bh + Ah*Bl + Al*Bh, fp32 accumulate (tensor cores, m16n8k16)
#define GBM 128
#define GBN 128
#define GBK 32
#define ASTR 40    // smem row stride in bf16: bank = (20r + c) % 32, conflict-free

#define MMA_BF16(d, av, b0, b1) \
    asm volatile("mma.sync.aligned.m16n8k16.row.col.f32.bf16.bf16.f32 " \
                 "{%0,%1,%2,%3}, {%4,%5,%6,%7}, {%8,%9}, {%0,%1,%2,%3};\n" \
                 : "+f"(d[0]), "+f"(d[1]), "+f"(d[2]), "+f"(d[3]) \
                 : "r"(av[0]), "r"(av[1]), "r"(av[2]), "r"(av[3]), \
                   "r"(b0), "r"(b1))

__global__ void __launch_bounds__(256, 2) gemm3_kernel(
    const __nv_bfloat16* __restrict__ AH, const __nv_bfloat16* __restrict__ AL,
    const __nv_bfloat16* __restrict__ BH, const __nv_bfloat16* __restrict__ BL,
    float* __restrict__ C, int K, int N)
{
    __shared__ __nv_bfloat16 sAH[GBM * ASTR], sAL[GBM * ASTR];
    __shared__ __nv_bfloat16 sBH[GBN * ASTR], sBL[GBN * ASTR];

    const int tid  = threadIdx.x;
    const int wid  = tid >> 5;
    const int lane = tid & 31;
    const int wm = (wid & 1) * 64;     // warp m offset within tile
    const int wn = (wid >> 1) * 32;    // warp n offset within tile
    const int m0 = blockIdx.y * GBM, n0 = blockIdx.x * GBN;

    float acc[4][4][4];
#pragma unroll
    for (int mt = 0; mt < 4; mt++)
#pragma unroll
        for (int nt = 0; nt < 4; nt++)
#pragma unroll
            for (int e = 0; e < 4; e++) acc[mt][nt][e] = 0.f;

    const int fr  = lane >> 2;         // fragment row 0..7
    const int fc  = (lane & 3) * 2;    // fragment k-pair base

    for (int k0 = 0; k0 < K; k0 += GBK) {
        // ---- global -> shared: 4 tiles of 128 rows x 32 bf16 ----
#pragma unroll
        for (int r = 0; r < 2; r++) {
            int slot = tid + 256 * r;          // 0..511
            int row  = slot >> 2;              // 0..127
            int q    = (slot & 3) * 8;         // bf16 col offset
            size_t ga = (size_t)(m0 + row) * K + k0 + q;
            size_t gb = (size_t)(n0 + row) * K + k0 + q;
            *(uint4*)&sAH[row * ASTR + q] = *(const uint4*)&AH[ga];
            *(uint4*)&sAL[row * ASTR + q] = *(const uint4*)&AL[ga];
            *(uint4*)&sBH[row * ASTR + q] = *(const uint4*)&BH[gb];
            *(uint4*)&sBL[row * ASTR + q] = *(const uint4*)&BL[gb];
        }
        __syncthreads();

#pragma unroll
        for (int kk = 0; kk < GBK; kk += 16) {
            // B fragments (kept live: BH reused for both A-hi and A-lo passes)
            uint32_t bh[4][2], bl[4][2];
#pragma unroll
            for (int nt = 0; nt < 4; nt++) {
                const __nv_bfloat16* p = &sBH[(wn + nt * 8 + fr) * ASTR + kk + fc];
                bh[nt][0] = *(const uint32_t*)p;
                bh[nt][1] = *(const uint32_t*)(p + 8);
                const __nv_bfloat16* q = &sBL[(wn + nt * 8 + fr) * ASTR + kk + fc];
                bl[nt][0] = *(const uint32_t*)q;
                bl[nt][1] = *(const uint32_t*)(q + 8);
            }
            // A-hi fragments
            uint32_t a[4][4];
#pragma unroll
            for (int mt = 0; mt < 4; mt++) {
                const __nv_bfloat16* p = &sAH[(wm + mt * 16 + fr) * ASTR + kk + fc];
                a[mt][0] = *(const uint32_t*)p;
                a[mt][1] = *(const uint32_t*)(p + 8 * ASTR);
                a[mt][2] = *(const uint32_t*)(p + 8);
                a[mt][3] = *(const uint32_t*)(p + 8 * ASTR + 8);
            }
            // Ah*Bh + Ah*Bl
#pragma unroll
            for (int mt = 0; mt < 4; mt++)
#pragma unroll
                for (int nt = 0; nt < 4; nt++) {
                    MMA_BF16(acc[mt][nt], a[mt], bh[nt][0], bh[nt][1]);
                    MMA_BF16(acc[mt][nt], a[mt], bl[nt][0], bl[nt][1]);
                }
            // A-lo fragments (overwrite)
#pragma unroll
            for (int mt = 0; mt < 4; mt++) {
                const __nv_bfloat16* p = &sAL[(wm + mt * 16 + fr) * ASTR + kk + fc];
                a[mt][0] = *(const uint32_t*)p;
                a[mt][1] = *(const uint32_t*)(p + 8 * ASTR);
                a[mt][2] = *(const uint32_t*)(p + 8);
                a[mt][3] = *(const uint32_t*)(p + 8 * ASTR + 8);
            }
            // Al*Bh
#pragma unroll
            for (int mt = 0; mt < 4; mt++)
#pragma unroll
                for (int nt = 0; nt < 4; nt++)
                    MMA_BF16(acc[mt][nt], a[mt], bh[nt][0], bh[nt][1]);
        }
        __syncthreads();
    }

    // ---- epilogue: fp32 store ----
#pragma unroll
    for (int mt = 0; mt < 4; mt++)
#pragma unroll
        for (int nt = 0; nt < 4; nt++) {
            size_t base = (size_t)(m0 + wm + mt * 16 + fr) * N + n0 + wn + nt * 8 + fc;
            *(float2*)&C[base]         = make_float2(acc[mt][nt][0], acc[mt][nt][1]);
            *(float2*)&C[base + 8 * (size_t)N] = make_float2(acc[mt][nt][2], acc[mt][nt][3]);
        }
}

// ---------------- RoPE (in-place, pair (d, d+32)) ----------------
__global__ void rope_kernel(float* __restrict__ p, const float* __restrict__ cosb,
                            const float* __restrict__ sinb, int nheads)
{
    int idx = blockIdx.x * blockDim.x + threadIdx.x;
    int total = MROWS * nheads * (DH / 2);
    if (idx >= total) return;
    int d   = idx & 31;
    int h   = (idx >> 5) % nheads;
    int bs  = idx / (nheads * 32);
    int s   = bs & (S_LEN - 1);
    size_t base = (size_t)bs * nheads * DH + h * DH;
    float x1 = p[base + d];
    float x2 = p[base + d + 32];
    float c1 = cosb[s * DH + d],      s1 = sinb[s * DH + d];
    float c2 = cosb[s * DH + d + 32], s2 = sinb[s * DH + d + 32];
    p[base + d]      = x1 * c1 - x2 * s1;
    p[base + d + 32] = x2 * c2 + x1 * s2;
}

// ---------------- Flash attention (causal, GQA), fp32; writes hi/lo bf16 ----------------
__global__ void __launch_bounds__(256) attn_kernel(
    const float* __restrict__ q, const float* __restrict__ k,
    const float* __restrict__ v, __nv_bfloat16* __restrict__ oH,
    __nv_bfloat16* __restrict__ oL)
{
    const int b   = blockIdx.z;
    const int h   = blockIdx.y;
    const int kvh = h >> 3;
    const int q0  = blockIdx.x * 64;
    const int tid = threadIdx.x;
    const int i   = tid >> 2;
    const int dsl = (tid & 3) * 16;

    __shared__ float ks[64][68];
    __shared__ float vs[64][68];

    float qreg[16];
    {
        const float* qp = q + (size_t)(b * S_LEN + q0 + i) * HQ + h * DH + dsl;
#pragma unroll
        for (int u = 0; u < 16; u += 4) {
            float4 t4 = *(const float4*)(qp + u);
            qreg[u] = t4.x; qreg[u + 1] = t4.y; qreg[u + 2] = t4.z; qreg[u + 3] = t4.w;
        }
    }

    float oacc[16];
#pragma unroll
    for (int u = 0; u < 16; u++) oacc[u] = 0.f;
    float mrow = -1e30f, lrow = 0.f;

    const float* kbase = k + (size_t)b * S_LEN * KVDIM + kvh * DH;
    const float* vbase = v + (size_t)b * S_LEN * KVDIM + kvh * DH;

    for (int j0 = 0; j0 <= q0; j0 += 64) {
#pragma unroll
        for (int r = 0; r < 4; r++) {
            int slot = tid + 256 * r;
            int row  = slot >> 4;
            int c4   = (slot & 15) * 4;
            *(float4*)&ks[row][c4] = *(const float4*)&kbase[(size_t)(j0 + row) * KVDIM + c4];
            *(float4*)&vs[row][c4] = *(const float4*)&vbase[(size_t)(j0 + row) * KVDIM + c4];
        }
        __syncthreads();

        const bool diag = (j0 == q0);
        for (int jc = 0; jc < 64; jc += 16) {
            float sc[16];
#pragma unroll
            for (int jj = 0; jj < 16; jj++) {
                int j = jc + jj;
                float dot = 0.f;
#pragma unroll
                for (int u = 0; u < 16; u += 4) {
                    float4 kv4 = *(const float4*)&ks[j][dsl + u];
                    dot = fmaf(qreg[u],     kv4.x, dot);
                    dot = fmaf(qreg[u + 1], kv4.y, dot);
                    dot = fmaf(qreg[u + 2], kv4.z, dot);
                    dot = fmaf(qreg[u + 3], kv4.w, dot);
                }
                dot += __shfl_xor_sync(0xffffffffu, dot, 1);
                dot += __shfl_xor_sync(0xffffffffu, dot, 2);
                dot *= 0.125f;
                if (diag && (j0 + j > q0 + i)) dot = -1e30f;
                sc[jj] = dot;
            }
            float mc = sc[0];
#pragma unroll
            for (int jj = 1; jj < 16; jj++) mc = fmaxf(mc, sc[jj]);
            float mnew  = fmaxf(mrow, mc);
            float scale = __expf(mrow - mnew);
            mrow = mnew;
            lrow *= scale;
#pragma unroll
            for (int u = 0; u < 16; u++) oacc[u] *= scale;

            float psum = 0.f;
#pragma unroll
            for (int jj = 0; jj < 16; jj++) {
                float p = (sc[jj] <= -1e29f) ? 0.f : __expf(sc[jj] - mnew);
                psum += p;
                int j = jc + jj;
#pragma unroll
                for (int u = 0; u < 16; u += 4) {
                    float4 vv = *(const float4*)&vs[j][dsl + u];
                    oacc[u]     = fmaf(p, vv.x, oacc[u]);
                    oacc[u + 1] = fmaf(p, vv.y, oacc[u + 1]);
                    oacc[u + 2] = fmaf(p, vv.z, oacc[u + 2]);
                    oacc[u + 3] = fmaf(p, vv.w, oacc[u + 3]);
                }
            }
            lrow += psum;
        }
        __syncthreads();
    }

    float inv = 1.f / lrow;
    size_t base = (size_t)(b * S_LEN + q0 + i) * HQ + h * DH + dsl;
#pragma unroll
    for (int u = 0; u < 16; u += 2) {
        float r0 = oacc[u] * inv, r1 = oacc[u + 1] * inv;
        __nv_bfloat16 h0 = __float2bfloat16(r0);
        __nv_bfloat16 h1 = __float2bfloat16(r1);
        __nv_bfloat16 l0 = __float2bfloat16(r0 - __bfloat162float(h0));
        __nv_bfloat16 l1 = __float2bfloat16(r1 - __bfloat162float(h1));
        *(__nv_bfloat162*)&oH[base + u] = __halves2bfloat162(h0, h1);
        *(__nv_bfloat162*)&oL[base + u] = __halves2bfloat162(l0, l1);
    }
}

// ---------------- launch ----------------
extern "C" void kernel_launch(void* const* d_in, const int* in_sizes, int n_in,
                              void* d_out, int out_size)
{
    const float* hs   = (const float*)d_in[0];
    const float* cosb = (const float*)d_in[3];
    const float* sinb = (const float*)d_in[4];
    const float* wq   = (const float*)d_in[5];
    const float* wk   = (const float*)d_in[6];
    const float* wv   = (const float*)d_in[7];
    const float* wd   = (const float*)d_in[8];
    float* out = (float*)d_out;

    float *pq, *pk, *pv;
    __nv_bfloat16 *hsH, *hsL, *aoH, *aoL, *wqH, *wqL, *wdH, *wdL, *wkH, *wkL, *wvH, *wvL;
    cudaGetSymbolAddress((void**)&pq,  g_q);
    cudaGetSymbolAddress((void**)&pk,  g_k);
    cudaGetSymbolAddress((void**)&pv,  g_v);
    cudaGetSymbolAddress((void**)&hsH, g_hsH); cudaGetSymbolAddress((void**)&hsL, g_hsL);
    cudaGetSymbolAddress((void**)&aoH, g_aoH); cudaGetSymbolAddress((void**)&aoL, g_aoL);
    cudaGetSymbolAddress((void**)&wqH, g_wqH); cudaGetSymbolAddress((void**)&wqL, g_wqL);
    cudaGetSymbolAddress((void**)&wdH, g_wdH); cudaGetSymbolAddress((void**)&wdL, g_wdL);
    cudaGetSymbolAddress((void**)&wkH, g_wkH); cudaGetSymbolAddress((void**)&wkL, g_wkL);
    cudaGetSymbolAddress((void**)&wvH, g_wvH); cudaGetSymbolAddress((void**)&wvL, g_wvL);

    // 1. split fp32 -> hi/lo bf16
    {
        int n4 = MROWS * HQ / 4;
        split_kernel<<<(n4 + 255) / 256, 256>>>(hs, hsH, hsL, n4);
        n4 = HQ * HQ / 4;
        split_kernel<<<(n4 + 255) / 256, 256>>>(wq, wqH, wqL, n4);
        split_kernel<<<(n4 + 255) / 256, 256>>>(wd, wdH, wdL, n4);
        n4 = KVDIM * HQ / 4;
        split_kernel<<<(n4 + 255) / 256, 256>>>(wk, wkH, wkL, n4);
        split_kernel<<<(n4 + 255) / 256, 256>>>(wv, wvH, wvL, n4);
    }

    // 2. projections on tensor cores
    gemm3_kernel<<<dim3(HQ / GBN, MROWS / GBM), 256>>>(hsH, hsL, wqH, wqL, pq, HQ, HQ);
    gemm3_kernel<<<dim3(KVDIM / GBN, MROWS / GBM), 256>>>(hsH, hsL, wkH, wkL, pk, HQ, KVDIM);
    gemm3_kernel<<<dim3(KVDIM / GBN, MROWS / GBM), 256>>>(hsH, hsL, wvH, wvL, pv, HQ, KVDIM);

    // 3. RoPE on q and k
    {
        int tq = MROWS * NH * (DH / 2);
        rope_kernel<<<(tq + 255) / 256, 256>>>(pq, cosb, sinb, NH);
        int tk = MROWS * NKV * (DH / 2);
        rope_kernel<<<(tk + 255) / 256, 256>>>(pk, cosb, sinb, NKV);
    }

    // 4. causal flash attention (writes hi/lo bf16 directly)
    attn_kernel<<<dim3(S_LEN / 64, NH, BDIM), 256>>>(pq, pk, pv, aoH, aoL);

    // 5. output projection
    gemm3_kernel<<<dim3(HQ / GBN, MROWS / GBM), 256>>>(aoH, aoL, wdH, wdL, out, HQ, HQ);
}

// round 9
// speedup vs baseline: 3.0811x; 2.1973x over previous
#include <cuda_runtime.h>
#include <cuda_bf16.h>
#include <cstdint>

#define S_LEN 1024
#define BDIM  2
#define HQ    4096
#define NKV   8
#define NH    64
#define DH    64
#define MROWS (BDIM * S_LEN)   // 2048
#define KVDIM (NKV * DH)       // 512

// ---------------- scratch (device globals; no allocs allowed) ----------------
__device__ float g_q [MROWS * HQ];
__device__ float g_k [MROWS * KVDIM];
__device__ float g_v [MROWS * KVDIM];
__device__ __nv_bfloat16 g_hsH[MROWS * HQ], g_hsL[MROWS * HQ];
__device__ __nv_bfloat16 g_aoH[MROWS * HQ], g_aoL[MROWS * HQ];
__device__ __nv_bfloat16 g_qsH[MROWS * HQ], g_qsL[MROWS * HQ];
__device__ __nv_bfloat16 g_ksH[MROWS * KVDIM], g_ksL[MROWS * KVDIM];
__device__ __nv_bfloat16 g_vtH[MROWS * KVDIM], g_vtL[MROWS * KVDIM];
__device__ __nv_bfloat16 g_wqH[HQ * HQ],    g_wqL[HQ * HQ];
__device__ __nv_bfloat16 g_wdH[HQ * HQ],    g_wdL[HQ * HQ];
__device__ __nv_bfloat16 g_wkH[KVDIM * HQ], g_wkL[KVDIM * HQ];
__device__ __nv_bfloat16 g_wvH[KVDIM * HQ], g_wvL[KVDIM * HQ];

// ---------------- helpers ----------------
__device__ __forceinline__ void split2(float x, float y, uint32_t& hi, uint32_t& lo)
{
    __nv_bfloat16 hx = __float2bfloat16(x), hy = __float2bfloat16(y);
    __nv_bfloat16 lx = __float2bfloat16(x - __bfloat162float(hx));
    __nv_bfloat16 ly = __float2bfloat16(y - __bfloat162float(hy));
    __nv_bfloat162 H = __halves2bfloat162(hx, hy);
    __nv_bfloat162 L = __halves2bfloat162(lx, ly);
    hi = *(uint32_t*)&H; lo = *(uint32_t*)&L;
}

#define MMA_BF16(d, av, b0, b1) \
    asm volatile("mma.sync.aligned.m16n8k16.row.col.f32.bf16.bf16.f32 " \
                 "{%0,%1,%2,%3}, {%4,%5,%6,%7}, {%8,%9}, {%0,%1,%2,%3};\n" \
                 : "+f"(d[0]), "+f"(d[1]), "+f"(d[2]), "+f"(d[3]) \
                 : "r"(av[0]), "r"(av[1]), "r"(av[2]), "r"(av[3]), \
                   "r"(b0), "r"(b1))

__device__ __forceinline__ void cp16(uint32_t sa, const void* g)
{
    asm volatile("cp.async.cg.shared.global [%0], [%1], 16;\n" :: "r"(sa), "l"(g));
}
#define CP_COMMIT() asm volatile("cp.async.commit_group;\n" ::: "memory")
#define CP_WAIT1()  asm volatile("cp.async.wait_group 1;\n" ::: "memory")

// ---------------- fp32 -> (hi, lo) bf16 split ----------------
__global__ void __launch_bounds__(256) split_kernel(
    const float* __restrict__ x, __nv_bfloat16* __restrict__ hi,
    __nv_bfloat16* __restrict__ lo, int n4)
{
    int i = blockIdx.x * blockDim.x + threadIdx.x;
    if (i >= n4) return;
    float4 v = ((const float4*)x)[i];
    uint32_t h0, l0, h1, l1;
    split2(v.x, v.y, h0, l0);
    split2(v.z, v.w, h1, l1);
    uint32_t* hp = (uint32_t*)hi + (size_t)i * 2;
    uint32_t* lp = (uint32_t*)lo + (size_t)i * 2;
    hp[0] = h0; hp[1] = h1;
    lp[0] = l0; lp[1] = l1;
}

// ---------------- bf16 split-GEMM, cp.async double-buffered ----------------
// C[m,n] = sum_k A[m,k]*W[n,k];  C = Ah*Bh + Al*Bh + Ah*Bl  (fp32 accum)
#define GBM 128
#define GBN 128
#define GBK 32
#define ASTR 40
#define GTILE (GBM * ASTR)            // elements per array per stage
#define GEMM_SMEM (2 * 4 * GTILE * 2) // bytes

__global__ void __launch_bounds__(256, 2) gemm3_kernel(
    const __nv_bfloat16* __restrict__ AH, const __nv_bfloat16* __restrict__ AL,
    const __nv_bfloat16* __restrict__ BH, const __nv_bfloat16* __restrict__ BL,
    float* __restrict__ C, int K, int N)
{
    extern __shared__ __nv_bfloat16 smem[];

    const int tid  = threadIdx.x;
    const int wid  = tid >> 5;
    const int lane = tid & 31;
    const int wm = (wid & 1) * 64;
    const int wn = (wid >> 1) * 32;
    const int m0 = blockIdx.y * GBM, n0 = blockIdx.x * GBN;
    const int fr = lane >> 2;
    const int fc = (lane & 3) * 2;

    float acc[4][4][4];
#pragma unroll
    for (int mt = 0; mt < 4; mt++)
#pragma unroll
        for (int nt = 0; nt < 4; nt++)
#pragma unroll
            for (int e = 0; e < 4; e++) acc[mt][nt][e] = 0.f;

    // stage loader: 4 arrays x 128 rows x 32 bf16
    auto load_stage = [&](int s, int k0) {
        __nv_bfloat16* base = smem + s * 4 * GTILE;
#pragma unroll
        for (int r = 0; r < 2; r++) {
            int slot = tid + 256 * r;
            int row  = slot >> 2;
            int q    = (slot & 3) * 8;
            size_t ga = (size_t)(m0 + row) * K + k0 + q;
            size_t gb = (size_t)(n0 + row) * K + k0 + q;
            uint32_t da = (uint32_t)__cvta_generic_to_shared(base + row * ASTR + q);
            cp16(da,             AH + ga);
            cp16(da + 2*GTILE,   AL + ga);
            cp16(da + 4*GTILE,   BH + gb);
            cp16(da + 6*GTILE,   BL + gb);
        }
    };

    load_stage(0, 0);
    CP_COMMIT();

    int s = 0;
    for (int k0 = 0; k0 < K; k0 += GBK) {
        if (k0 + GBK < K) load_stage(s ^ 1, k0 + GBK);
        CP_COMMIT();
        CP_WAIT1();
        __syncthreads();

        const __nv_bfloat16* sAH = smem + s * 4 * GTILE;
        const __nv_bfloat16* sAL = sAH + GTILE;
        const __nv_bfloat16* sBH = sAH + 2 * GTILE;
        const __nv_bfloat16* sBL = sAH + 3 * GTILE;

#pragma unroll
        for (int kk = 0; kk < GBK; kk += 16) {
            uint32_t bh[4][2], bl[4][2];
#pragma unroll
            for (int nt = 0; nt < 4; nt++) {
                const __nv_bfloat16* p = &sBH[(wn + nt * 8 + fr) * ASTR + kk + fc];
                bh[nt][0] = *(const uint32_t*)p;
                bh[nt][1] = *(const uint32_t*)(p + 8);
                const __nv_bfloat16* q = &sBL[(wn + nt * 8 + fr) * ASTR + kk + fc];
                bl[nt][0] = *(const uint32_t*)q;
                bl[nt][1] = *(const uint32_t*)(q + 8);
            }
            uint32_t a[4][4];
#pragma unroll
            for (int mt = 0; mt < 4; mt++) {
                const __nv_bfloat16* p = &sAH[(wm + mt * 16 + fr) * ASTR + kk + fc];
                a[mt][0] = *(const uint32_t*)p;
                a[mt][1] = *(const uint32_t*)(p + 8 * ASTR);
                a[mt][2] = *(const uint32_t*)(p + 8);
                a[mt][3] = *(const uint32_t*)(p + 8 * ASTR + 8);
            }
#pragma unroll
            for (int mt = 0; mt < 4; mt++)
#pragma unroll
                for (int nt = 0; nt < 4; nt++) {
                    MMA_BF16(acc[mt][nt], a[mt], bh[nt][0], bh[nt][1]);
                    MMA_BF16(acc[mt][nt], a[mt], bl[nt][0], bl[nt][1]);
                }
#pragma unroll
            for (int mt = 0; mt < 4; mt++) {
                const __nv_bfloat16* p = &sAL[(wm + mt * 16 + fr) * ASTR + kk + fc];
                a[mt][0] = *(const uint32_t*)p;
                a[mt][1] = *(const uint32_t*)(p + 8 * ASTR);
                a[mt][2] = *(const uint32_t*)(p + 8);
                a[mt][3] = *(const uint32_t*)(p + 8 * ASTR + 8);
            }
#pragma unroll
            for (int mt = 0; mt < 4; mt++)
#pragma unroll
                for (int nt = 0; nt < 4; nt++)
                    MMA_BF16(acc[mt][nt], a[mt], bh[nt][0], bh[nt][1]);
        }
        __syncthreads();
        s ^= 1;
    }

#pragma unroll
    for (int mt = 0; mt < 4; mt++)
#pragma unroll
        for (int nt = 0; nt < 4; nt++) {
            size_t base = (size_t)(m0 + wm + mt * 16 + fr) * N + n0 + wn + nt * 8 + fc;
            *(float2*)&C[base]                 = make_float2(acc[mt][nt][0], acc[mt][nt][1]);
            *(float2*)&C[base + 8 * (size_t)N] = make_float2(acc[mt][nt][2], acc[mt][nt][3]);
        }
}

// ---------------- RoPE + hi/lo split (q: scale=0.125 folded; k: scale=1) ----------------
__global__ void rope_split_kernel(
    const float* __restrict__ p, const float* __restrict__ cosb,
    const float* __restrict__ sinb, __nv_bfloat16* __restrict__ outH,
    __nv_bfloat16* __restrict__ outL, int nheads, float scl)
{
    int idx = blockIdx.x * blockDim.x + threadIdx.x;
    int total = MROWS * nheads * (DH / 2);
    if (idx >= total) return;
    int d  = idx & 31;
    int h  = (idx >> 5) % nheads;
    int bs = idx / (nheads * 32);
    int s  = bs & (S_LEN - 1);
    size_t base = (size_t)bs * nheads * DH + h * DH;
    float x1 = p[base + d];
    float x2 = p[base + d + 32];
    float c1 = cosb[s * DH + d],      s1 = sinb[s * DH + d];
    float c2 = cosb[s * DH + d + 32], s2 = sinb[s * DH + d + 32];
    float y1 = (x1 * c1 - x2 * s1) * scl;
    float y2 = (x2 * c2 + x1 * s2) * scl;
    __nv_bfloat16 h1 = __float2bfloat16(y1);
    __nv_bfloat16 h2 = __float2bfloat16(y2);
    outH[base + d]      = h1;
    outH[base + d + 32] = h2;
    outL[base + d]      = __float2bfloat16(y1 - __bfloat162float(h1));
    outL[base + d + 32] = __float2bfloat16(y2 - __bfloat162float(h2));
}

// ---------------- V split + transpose: g_v[b*S+s][kvh*64+d] -> vt[(b*NKV+kvh)*64+d][s] ----------------
__global__ void __launch_bounds__(256) splitvt_kernel(
    const float* __restrict__ v, __nv_bfloat16* __restrict__ vtH,
    __nv_bfloat16* __restrict__ vtL)
{
    __shared__ float sm[64][65];
    const int s0  = blockIdx.x * 64;
    const int kvh = blockIdx.y;
    const int b   = blockIdx.z;
    const int tid = threadIdx.x;

#pragma unroll
    for (int r = 0; r < 16; r++) {
        int slot = tid + 256 * r;
        int sl = slot >> 6;       // s local
        int d  = slot & 63;
        sm[d][sl] = v[(size_t)(b * S_LEN + s0 + sl) * KVDIM + kvh * DH + d];
    }
    __syncthreads();
#pragma unroll
    for (int r = 0; r < 16; r++) {
        int slot = tid + 256 * r;
        int d  = slot >> 6;
        int sl = slot & 63;
        float x = sm[d][sl];
        __nv_bfloat16 h = __float2bfloat16(x);
        size_t o = ((size_t)((b * NKV + kvh) * DH + d)) * S_LEN + s0 + sl;
        vtH[o] = h;
        vtL[o] = __float2bfloat16(x - __bfloat162float(h));
    }
}

// ---------------- Flash attention on tensor cores (causal, GQA, split bf16) ----------------
#define ATS 72

__global__ void __launch_bounds__(128) attn_mma_kernel(
    const __nv_bfloat16* __restrict__ qH, const __nv_bfloat16* __restrict__ qL,
    const __nv_bfloat16* __restrict__ kH, const __nv_bfloat16* __restrict__ kL,
    const __nv_bfloat16* __restrict__ vH, const __nv_bfloat16* __restrict__ vL,
    __nv_bfloat16* __restrict__ oH, __nv_bfloat16* __restrict__ oL)
{
    __shared__ __nv_bfloat16 sKH[64 * ATS], sKL[64 * ATS];
    __shared__ __nv_bfloat16 sVH[64 * ATS], sVL[64 * ATS];

    const int b   = blockIdx.z;
    const int h   = blockIdx.y;
    const int kvh = h >> 3;
    const int q0  = blockIdx.x * 64;
    const int tid  = threadIdx.x;
    const int w    = tid >> 5;
    const int lane = tid & 31;
    const int fr = lane >> 2;
    const int fc = (lane & 3) * 2;
    const int qrow = q0 + w * 16;

    // Q fragments (hi/lo) for this warp's 16 rows, all 4 k-chunks
    uint32_t aH[4][4], aL[4][4];
    {
        const __nv_bfloat16* p0 = qH + (size_t)(b * S_LEN + qrow + fr) * HQ + h * DH + fc;
        const __nv_bfloat16* p1 = qL + (size_t)(b * S_LEN + qrow + fr) * HQ + h * DH + fc;
#pragma unroll
        for (int kc = 0; kc < 4; kc++) {
            aH[kc][0] = *(const uint32_t*)(p0 + kc * 16);
            aH[kc][1] = *(const uint32_t*)(p0 + kc * 16 + 8 * HQ);
            aH[kc][2] = *(const uint32_t*)(p0 + kc * 16 + 8);
            aH[kc][3] = *(const uint32_t*)(p0 + kc * 16 + 8 * HQ + 8);
            aL[kc][0] = *(const uint32_t*)(p1 + kc * 16);
            aL[kc][1] = *(const uint32_t*)(p1 + kc * 16 + 8 * HQ);
            aL[kc][2] = *(const uint32_t*)(p1 + kc * 16 + 8);
            aL[kc][3] = *(const uint32_t*)(p1 + kc * 16 + 8 * HQ + 8);
        }
    }

    float oacc[8][4];
#pragma unroll
    for (int nt = 0; nt < 8; nt++)
#pragma unroll
        for (int e = 0; e < 4; e++) oacc[nt][e] = 0.f;
    float mrow0 = -1e30f, mrow1 = -1e30f, lrow0 = 0.f, lrow1 = 0.f;

    const __nv_bfloat16* kHb = kH + (size_t)b * S_LEN * KVDIM + kvh * DH;
    const __nv_bfloat16* kLb = kL + (size_t)b * S_LEN * KVDIM + kvh * DH;
    const __nv_bfloat16* vHb = vH + ((size_t)(b * NKV + kvh) * DH) * S_LEN;
    const __nv_bfloat16* vLb = vL + ((size_t)(b * NKV + kvh) * DH) * S_LEN;

    for (int j0 = 0; j0 <= q0; j0 += 64) {
        // load K (as [key][d]) and V (as [d][key]) tiles
#pragma unroll
        for (int it = 0; it < 4; it++) {
            int slot = tid + 128 * it;
            int row = slot >> 3;
            int c   = (slot & 7) * 8;
            *(uint4*)&sKH[row * ATS + c] = *(const uint4*)&kHb[(size_t)(j0 + row) * KVDIM + c];
            *(uint4*)&sKL[row * ATS + c] = *(const uint4*)&kLb[(size_t)(j0 + row) * KVDIM + c];
            *(uint4*)&sVH[row * ATS + c] = *(const uint4*)&vHb[(size_t)row * S_LEN + j0 + c];
            *(uint4*)&sVL[row * ATS + c] = *(const uint4*)&vLb[(size_t)row * S_LEN + j0 + c];
        }
        __syncthreads();

        // ---- scores: S = Qh*Kh + Ql*Kh + Qh*Kl ----
        float sc[8][4];
#pragma unroll
        for (int nt = 0; nt < 8; nt++)
#pragma unroll
            for (int e = 0; e < 4; e++) sc[nt][e] = 0.f;

#pragma unroll
        for (int nt = 0; nt < 8; nt++)
#pragma unroll
            for (int kc = 0; kc < 4; kc++) {
                const __nv_bfloat16* kp = &sKH[(nt * 8 + fr) * ATS + kc * 16 + fc];
                uint32_t b0 = *(const uint32_t*)kp, b1 = *(const uint32_t*)(kp + 8);
                MMA_BF16(sc[nt], aH[kc], b0, b1);
                MMA_BF16(sc[nt], aL[kc], b0, b1);
                const __nv_bfloat16* kq = &sKL[(nt * 8 + fr) * ATS + kc * 16 + fc];
                uint32_t c0 = *(const uint32_t*)kq, c1 = *(const uint32_t*)(kq + 8);
                MMA_BF16(sc[nt], aH[kc], c0, c1);
            }

        if (j0 == q0) {
#pragma unroll
            for (int nt = 0; nt < 8; nt++) {
                int col = j0 + nt * 8 + fc;
                int r0 = qrow + fr, r1 = r0 + 8;
                if (col     > r0) sc[nt][0] = -1e30f;
                if (col + 1 > r0) sc[nt][1] = -1e30f;
                if (col     > r1) sc[nt][2] = -1e30f;
                if (col + 1 > r1) sc[nt][3] = -1e30f;
            }
        }

        // ---- online softmax (rows fr and fr+8) ----
        float mc0 = -1e30f, mc1 = -1e30f;
#pragma unroll
        for (int nt = 0; nt < 8; nt++) {
            mc0 = fmaxf(mc0, fmaxf(sc[nt][0], sc[nt][1]));
            mc1 = fmaxf(mc1, fmaxf(sc[nt][2], sc[nt][3]));
        }
        mc0 = fmaxf(mc0, __shfl_xor_sync(0xffffffffu, mc0, 1));
        mc0 = fmaxf(mc0, __shfl_xor_sync(0xffffffffu, mc0, 2));
        mc1 = fmaxf(mc1, __shfl_xor_sync(0xffffffffu, mc1, 1));
        mc1 = fmaxf(mc1, __shfl_xor_sync(0xffffffffu, mc1, 2));

        float mn0 = fmaxf(mrow0, mc0), mn1 = fmaxf(mrow1, mc1);
        float scale0 = __expf(mrow0 - mn0), scale1 = __expf(mrow1 - mn1);
        mrow0 = mn0; mrow1 = mn1;
#pragma unroll
        for (int nt = 0; nt < 8; nt++) {
            oacc[nt][0] *= scale0; oacc[nt][1] *= scale0;
            oacc[nt][2] *= scale1; oacc[nt][3] *= scale1;
        }
        float rs0 = 0.f, rs1 = 0.f;
#pragma unroll
        for (int nt = 0; nt < 8; nt++) {
            sc[nt][0] = __expf(sc[nt][0] - mn0);
            sc[nt][1] = __expf(sc[nt][1] - mn0);
            sc[nt][2] = __expf(sc[nt][2] - mn1);
            sc[nt][3] = __expf(sc[nt][3] - mn1);
            rs0 += sc[nt][0] + sc[nt][1];
            rs1 += sc[nt][2] + sc[nt][3];
        }
        rs0 += __shfl_xor_sync(0xffffffffu, rs0, 1);
        rs0 += __shfl_xor_sync(0xffffffffu, rs0, 2);
        rs1 += __shfl_xor_sync(0xffffffffu, rs1, 1);
        rs1 += __shfl_xor_sync(0xffffffffu, rs1, 2);
        lrow0 = lrow0 * scale0 + rs0;
        lrow1 = lrow1 * scale1 + rs1;

        // ---- O += Ph*Vh + Pl*Vh + Ph*Vl ----
#pragma unroll
        for (int kc = 0; kc < 4; kc++) {
            uint32_t ph[4], pl[4];
            split2(sc[2 * kc][0],     sc[2 * kc][1],     ph[0], pl[0]);
            split2(sc[2 * kc][2],     sc[2 * kc][3],     ph[1], pl[1]);
            split2(sc[2 * kc + 1][0], sc[2 * kc + 1][1], ph[2], pl[2]);
            split2(sc[2 * kc + 1][2], sc[2 * kc + 1][3], ph[3], pl[3]);
#pragma unroll
            for (int nt = 0; nt < 8; nt++) {
                const __nv_bfloat16* vp = &sVH[(nt * 8 + fr) * ATS + kc * 16 + fc];
                uint32_t b0 = *(const uint32_t*)vp, b1 = *(const uint32_t*)(vp + 8);
                MMA_BF16(oacc[nt], ph, b0, b1);
                MMA_BF16(oacc[nt], pl, b0, b1);
                const __nv_bfloat16* vq = &sVL[(nt * 8 + fr) * ATS + kc * 16 + fc];
                uint32_t c0 = *(const uint32_t*)vq, c1 = *(const uint32_t*)(vq + 8);
                MMA_BF16(oacc[nt], ph, c0, c1);
            }
        }
        __syncthreads();
    }

    // ---- finalize: normalize, hi/lo split, store ----
    float inv0 = 1.f / lrow0, inv1 = 1.f / lrow1;
    size_t o0 = (size_t)(b * S_LEN + qrow + fr) * HQ + h * DH + fc;
#pragma unroll
    for (int nt = 0; nt < 8; nt++) {
        uint32_t h0, l0, h1, l1;
        split2(oacc[nt][0] * inv0, oacc[nt][1] * inv0, h0, l0);
        split2(oacc[nt][2] * inv1, oacc[nt][3] * inv1, h1, l1);
        *(uint32_t*)&oH[o0 + nt * 8]          = h0;
        *(uint32_t*)&oL[o0 + nt * 8]          = l0;
        *(uint32_t*)&oH[o0 + 8 * HQ + nt * 8] = h1;
        *(uint32_t*)&oL[o0 + 8 * HQ + nt * 8] = l1;
    }
}

// ---------------- launch ----------------
extern "C" void kernel_launch(void* const* d_in, const int* in_sizes, int n_in,
                              void* d_out, int out_size)
{
    const float* hs   = (const float*)d_in[0];
    const float* cosb = (const float*)d_in[3];
    const float* sinb = (const float*)d_in[4];
    const float* wq   = (const float*)d_in[5];
    const float* wk   = (const float*)d_in[6];
    const float* wv   = (const float*)d_in[7];
    const float* wd   = (const float*)d_in[8];
    float* out = (float*)d_out;

    float *pq, *pk, *pv;
    __nv_bfloat16 *hsH, *hsL, *aoH, *aoL, *qsH, *qsL, *ksH, *ksL, *vtH, *vtL;
    __nv_bfloat16 *wqH, *wqL, *wdH, *wdL, *wkH, *wkL, *wvH, *wvL;
    cudaGetSymbolAddress((void**)&pq,  g_q);
    cudaGetSymbolAddress((void**)&pk,  g_k);
    cudaGetSymbolAddress((void**)&pv,  g_v);
    cudaGetSymbolAddress((void**)&hsH, g_hsH); cudaGetSymbolAddress((void**)&hsL, g_hsL);
    cudaGetSymbolAddress((void**)&aoH, g_aoH); cudaGetSymbolAddress((void**)&aoL, g_aoL);
    cudaGetSymbolAddress((void**)&qsH, g_qsH); cudaGetSymbolAddress((void**)&qsL, g_qsL);
    cudaGetSymbolAddress((void**)&ksH, g_ksH); cudaGetSymbolAddress((void**)&ksL, g_ksL);
    cudaGetSymbolAddress((void**)&vtH, g_vtH); cudaGetSymbolAddress((void**)&vtL, g_vtL);
    cudaGetSymbolAddress((void**)&wqH, g_wqH); cudaGetSymbolAddress((void**)&wqL, g_wqL);
    cudaGetSymbolAddress((void**)&wdH, g_wdH); cudaGetSymbolAddress((void**)&wdL, g_wdL);
    cudaGetSymbolAddress((void**)&wkH, g_wkH); cudaGetSymbolAddress((void**)&wkL, g_wkL);
    cudaGetSymbolAddress((void**)&wvH, g_wvH); cudaGetSymbolAddress((void**)&wvL, g_wvL);

    static bool attr_set = false;
    if (!attr_set) {
        cudaFuncSetAttribute(gemm3_kernel,
                             cudaFuncAttributeMaxDynamicSharedMemorySize, GEMM_SMEM);
        attr_set = true;
    }

    // 1. splits
    {
        int n4 = MROWS * HQ / 4;
        split_kernel<<<(n4 + 255) / 256, 256>>>(hs, hsH, hsL, n4);
        n4 = HQ * HQ / 4;
        split_kernel<<<(n4 + 255) / 256, 256>>>(wq, wqH, wqL, n4);
        split_kernel<<<(n4 + 255) / 256, 256>>>(wd, wdH, wdL, n4);
        n4 = KVDIM * HQ / 4;
        split_kernel<<<(n4 + 255) / 256, 256>>>(wk, wkH, wkL, n4);
        split_kernel<<<(n4 + 255) / 256, 256>>>(wv, wvH, wvL, n4);
    }

    // 2. projections (tensor cores, cp.async pipelined)
    gemm3_kernel<<<dim3(HQ / GBN, MROWS / GBM), 256, GEMM_SMEM>>>(hsH, hsL, wqH, wqL, pq, HQ, HQ);
    gemm3_kernel<<<dim3(KVDIM / GBN, MROWS / GBM), 256, GEMM_SMEM>>>(hsH, hsL, wkH, wkL, pk, HQ, KVDIM);
    gemm3_kernel<<<dim3(KVDIM / GBN, MROWS / GBM), 256, GEMM_SMEM>>>(hsH, hsL, wvH, wvL, pv, HQ, KVDIM);

    // 3. RoPE + split (q has 1/sqrt(D) folded in), V transpose+split
    {
        int tq = MROWS * NH * (DH / 2);
        rope_split_kernel<<<(tq + 255) / 256, 256>>>(pq, cosb, sinb, qsH, qsL, NH, 0.125f);
        int tk = MROWS * NKV * (DH / 2);
        rope_split_kernel<<<(tk + 255) / 256, 256>>>(pk, cosb, sinb, ksH, ksL, NKV, 1.0f);
        splitvt_kernel<<<dim3(S_LEN / 64, NKV, BDIM), 256>>>(pv, vtH, vtL);
    }

    // 4. tensor-core causal flash attention
    attn_mma_kernel<<<dim3(S_LEN / 64, NH, BDIM), 128>>>(qsH, qsL, ksH, ksL, vtH, vtL, aoH, aoL);

    // 5. output projection
    gemm3_kernel<<<dim3(HQ / GBN, MROWS / GBM), 256, GEMM_SMEM>>>(aoH, aoL, wdH, wdL, out, HQ, HQ);
}

// round 11
// speedup vs baseline: 3.4627x; 1.1238x over previous
#include <cuda_runtime.h>
#include <cuda_bf16.h>
#include <cstdint>

#define S_LEN 1024
#define BDIM  2
#define HQ    4096
#define NKV   8
#define NH    64
#define DH    64
#define MROWS (BDIM * S_LEN)   // 2048
#define KVDIM (NKV * DH)       // 512

// ---------------- scratch (device globals; no allocs allowed) ----------------
__device__ float g_q [MROWS * HQ];
__device__ float g_k [MROWS * KVDIM];
__device__ float g_v [MROWS * KVDIM];
__device__ __nv_bfloat16 g_hsH[MROWS * HQ], g_hsL[MROWS * HQ];
__device__ __nv_bfloat16 g_aoH[MROWS * HQ], g_aoL[MROWS * HQ];
__device__ __nv_bfloat16 g_qsH[MROWS * HQ], g_qsL[MROWS * HQ];
__device__ __nv_bfloat16 g_ksH[MROWS * KVDIM], g_ksL[MROWS * KVDIM];
__device__ __nv_bfloat16 g_vtH[MROWS * KVDIM], g_vtL[MROWS * KVDIM];
__device__ __nv_bfloat16 g_wqH[HQ * HQ],    g_wqL[HQ * HQ];
__device__ __nv_bfloat16 g_wdH[HQ * HQ],    g_wdL[HQ * HQ];
__device__ __nv_bfloat16 g_wkH[KVDIM * HQ], g_wkL[KVDIM * HQ];
__device__ __nv_bfloat16 g_wvH[KVDIM * HQ], g_wvL[KVDIM * HQ];

// ---------------- helpers ----------------
__device__ __forceinline__ void split2(float x, float y, uint32_t& hi, uint32_t& lo)
{
    __nv_bfloat16 hx = __float2bfloat16(x), hy = __float2bfloat16(y);
    __nv_bfloat16 lx = __float2bfloat16(x - __bfloat162float(hx));
    __nv_bfloat16 ly = __float2bfloat16(y - __bfloat162float(hy));
    __nv_bfloat162 H = __halves2bfloat162(hx, hy);
    __nv_bfloat162 L = __halves2bfloat162(lx, ly);
    hi = *(uint32_t*)&H; lo = *(uint32_t*)&L;
}

#define MMA_BF16(d, av, b0, b1) \
    asm volatile("mma.sync.aligned.m16n8k16.row.col.f32.bf16.bf16.f32 " \
                 "{%0,%1,%2,%3}, {%4,%5,%6,%7}, {%8,%9}, {%0,%1,%2,%3};\n" \
                 : "+f"(d[0]), "+f"(d[1]), "+f"(d[2]), "+f"(d[3]) \
                 : "r"(av[0]), "r"(av[1]), "r"(av[2]), "r"(av[3]), \
                   "r"(b0), "r"(b1))

__device__ __forceinline__ void cp16(uint32_t sa, const void* g)
{
    asm volatile("cp.async.cg.shared.global [%0], [%1], 16;\n" :: "r"(sa), "l"(g));
}
#define CP_COMMIT() asm volatile("cp.async.commit_group;\n" ::: "memory")
#define CP_WAIT1()  asm volatile("cp.async.wait_group 1;\n" ::: "memory")

// ---------------- fp32 -> (hi, lo) bf16 split ----------------
__global__ void __launch_bounds__(256) split_kernel(
    const float* __restrict__ x, __nv_bfloat16* __restrict__ hi,
    __nv_bfloat16* __restrict__ lo, int n4)
{
    int i = blockIdx.x * blockDim.x + threadIdx.x;
    if (i >= n4) return;
    float4 v = ((const float4*)x)[i];
    uint32_t h0, l0, h1, l1;
    split2(v.x, v.y, h0, l0);
    split2(v.z, v.w, h1, l1);
    uint32_t* hp = (uint32_t*)hi + (size_t)i * 2;
    uint32_t* lp = (uint32_t*)lo + (size_t)i * 2;
    hp[0] = h0; hp[1] = h1;
    lp[0] = l0; lp[1] = l1;
}

// ---------------- bf16 split-GEMM, cp.async double-buffered ----------------
// C[m,n] = sum_k A[m,k]*W[n,k];  C = Ah*Bh + Al*Bh + Ah*Bl  (fp32 accum)
#define GBM 128
#define GBN 128
#define GBK 32
#define ASTR 40
#define GTILE (GBM * ASTR)            // elements per array per stage
#define GEMM_SMEM (2 * 4 * GTILE * 2) // bytes

__device__ __forceinline__ void gemm3_body(
    const __nv_bfloat16* __restrict__ AH, const __nv_bfloat16* __restrict__ AL,
    const __nv_bfloat16* __restrict__ BH, const __nv_bfloat16* __restrict__ BL,
    float* __restrict__ C, int K, int N, int m0, int n0, __nv_bfloat16* smem)
{
    const int tid  = threadIdx.x;
    const int wid  = tid >> 5;
    const int lane = tid & 31;
    const int wm = (wid & 1) * 64;
    const int wn = (wid >> 1) * 32;
    const int fr = lane >> 2;
    const int fc = (lane & 3) * 2;

    float acc[4][4][4];
#pragma unroll
    for (int mt = 0; mt < 4; mt++)
#pragma unroll
        for (int nt = 0; nt < 4; nt++)
#pragma unroll
            for (int e = 0; e < 4; e++) acc[mt][nt][e] = 0.f;

    auto load_stage = [&](int s, int k0) {
        __nv_bfloat16* base = smem + s * 4 * GTILE;
#pragma unroll
        for (int r = 0; r < 2; r++) {
            int slot = tid + 256 * r;
            int row  = slot >> 2;
            int q    = (slot & 3) * 8;
            size_t ga = (size_t)(m0 + row) * K + k0 + q;
            size_t gb = (size_t)(n0 + row) * K + k0 + q;
            uint32_t da = (uint32_t)__cvta_generic_to_shared(base + row * ASTR + q);
            cp16(da,             AH + ga);
            cp16(da + 2*GTILE,   AL + ga);
            cp16(da + 4*GTILE,   BH + gb);
            cp16(da + 6*GTILE,   BL + gb);
        }
    };

    load_stage(0, 0);
    CP_COMMIT();

    int s = 0;
    for (int k0 = 0; k0 < K; k0 += GBK) {
        if (k0 + GBK < K) load_stage(s ^ 1, k0 + GBK);
        CP_COMMIT();
        CP_WAIT1();
        __syncthreads();

        const __nv_bfloat16* sAH = smem + s * 4 * GTILE;
        const __nv_bfloat16* sAL = sAH + GTILE;
        const __nv_bfloat16* sBH = sAH + 2 * GTILE;
        const __nv_bfloat16* sBL = sAH + 3 * GTILE;

#pragma unroll
        for (int kk = 0; kk < GBK; kk += 16) {
            uint32_t bh[4][2], bl[4][2];
#pragma unroll
            for (int nt = 0; nt < 4; nt++) {
                const __nv_bfloat16* p = &sBH[(wn + nt * 8 + fr) * ASTR + kk + fc];
                bh[nt][0] = *(const uint32_t*)p;
                bh[nt][1] = *(const uint32_t*)(p + 8);
                const __nv_bfloat16* q = &sBL[(wn + nt * 8 + fr) * ASTR + kk + fc];
                bl[nt][0] = *(const uint32_t*)q;
                bl[nt][1] = *(const uint32_t*)(q + 8);
            }
            uint32_t a[4][4];
#pragma unroll
            for (int mt = 0; mt < 4; mt++) {
                const __nv_bfloat16* p = &sAH[(wm + mt * 16 + fr) * ASTR + kk + fc];
                a[mt][0] = *(const uint32_t*)p;
                a[mt][1] = *(const uint32_t*)(p + 8 * ASTR);
                a[mt][2] = *(const uint32_t*)(p + 8);
                a[mt][3] = *(const uint32_t*)(p + 8 * ASTR + 8);
            }
#pragma unroll
            for (int mt = 0; mt < 4; mt++)
#pragma unroll
                for (int nt = 0; nt < 4; nt++) {
                    MMA_BF16(acc[mt][nt], a[mt], bh[nt][0], bh[nt][1]);
                    MMA_BF16(acc[mt][nt], a[mt], bl[nt][0], bl[nt][1]);
                }
#pragma unroll
            for (int mt = 0; mt < 4; mt++) {
                const __nv_bfloat16* p = &sAL[(wm + mt * 16 + fr) * ASTR + kk + fc];
                a[mt][0] = *(const uint32_t*)p;
                a[mt][1] = *(const uint32_t*)(p + 8 * ASTR);
                a[mt][2] = *(const uint32_t*)(p + 8);
                a[mt][3] = *(const uint32_t*)(p + 8 * ASTR + 8);
            }
#pragma unroll
            for (int mt = 0; mt < 4; mt++)
#pragma unroll
                for (int nt = 0; nt < 4; nt++)
                    MMA_BF16(acc[mt][nt], a[mt], bh[nt][0], bh[nt][1]);
        }
        __syncthreads();
        s ^= 1;
    }

#pragma unroll
    for (int mt = 0; mt < 4; mt++)
#pragma unroll
        for (int nt = 0; nt < 4; nt++) {
            size_t base = (size_t)(m0 + wm + mt * 16 + fr) * N + n0 + wn + nt * 8 + fc;
            *(float2*)&C[base]                 = make_float2(acc[mt][nt][0], acc[mt][nt][1]);
            *(float2*)&C[base + 8 * (size_t)N] = make_float2(acc[mt][nt][2], acc[mt][nt][3]);
        }
}

__global__ void __launch_bounds__(256, 2) gemm3_kernel(
    const __nv_bfloat16* __restrict__ AH, const __nv_bfloat16* __restrict__ AL,
    const __nv_bfloat16* __restrict__ BH, const __nv_bfloat16* __restrict__ BL,
    float* __restrict__ C, int K, int N)
{
    extern __shared__ __nv_bfloat16 smem[];
    gemm3_body(AH, AL, BH, BL, C, K, N, blockIdx.y * GBM, blockIdx.x * GBN, smem);
}

// fused K+V projection: grid.x = 8; 0..3 -> K, 4..7 -> V (one 128-CTA wave)
__global__ void __launch_bounds__(256, 2) gemm3_kv_kernel(
    const __nv_bfloat16* __restrict__ AH, const __nv_bfloat16* __restrict__ AL,
    const __nv_bfloat16* __restrict__ KH, const __nv_bfloat16* __restrict__ KL,
    const __nv_bfloat16* __restrict__ VH, const __nv_bfloat16* __restrict__ VL,
    float* __restrict__ Ck, float* __restrict__ Cv)
{
    extern __shared__ __nv_bfloat16 smem[];
    const __nv_bfloat16 *BH, *BL;
    float* C;
    int n0;
    if (blockIdx.x < 4) { BH = KH; BL = KL; C = Ck; n0 = blockIdx.x * GBN; }
    else                { BH = VH; BL = VL; C = Cv; n0 = (blockIdx.x - 4) * GBN; }
    gemm3_body(AH, AL, BH, BL, C, HQ, KVDIM, blockIdx.y * GBM, n0, smem);
}

// ---------------- RoPE + hi/lo split (q: scale=0.125 folded; k: scale=1) ----------------
__global__ void rope_split_kernel(
    const float* __restrict__ p, const float* __restrict__ cosb,
    const float* __restrict__ sinb, __nv_bfloat16* __restrict__ outH,
    __nv_bfloat16* __restrict__ outL, int nheads, float scl)
{
    int idx = blockIdx.x * blockDim.x + threadIdx.x;
    int total = MROWS * nheads * (DH / 2);
    if (idx >= total) return;
    int d  = idx & 31;
    int h  = (idx >> 5) % nheads;
    int bs = idx / (nheads * 32);
    int s  = bs & (S_LEN - 1);
    size_t base = (size_t)bs * nheads * DH + h * DH;
    float x1 = p[base + d];
    float x2 = p[base + d + 32];
    float c1 = cosb[s * DH + d],      s1 = sinb[s * DH + d];
    float c2 = cosb[s * DH + d + 32], s2 = sinb[s * DH + d + 32];
    float y1 = (x1 * c1 - x2 * s1) * scl;
    float y2 = (x2 * c2 + x1 * s2) * scl;
    __nv_bfloat16 h1 = __float2bfloat16(y1);
    __nv_bfloat16 h2 = __float2bfloat16(y2);
    outH[base + d]      = h1;
    outH[base + d + 32] = h2;
    outL[base + d]      = __float2bfloat16(y1 - __bfloat162float(h1));
    outL[base + d + 32] = __float2bfloat16(y2 - __bfloat162float(h2));
}

// ---------------- V split + transpose ----------------
__global__ void __launch_bounds__(256) splitvt_kernel(
    const float* __restrict__ v, __nv_bfloat16* __restrict__ vtH,
    __nv_bfloat16* __restrict__ vtL)
{
    __shared__ float sm[64][65];
    const int s0  = blockIdx.x * 64;
    const int kvh = blockIdx.y;
    const int b   = blockIdx.z;
    const int tid = threadIdx.x;

#pragma unroll
    for (int r = 0; r < 16; r++) {
        int slot = tid + 256 * r;
        int sl = slot >> 6;
        int d  = slot & 63;
        sm[d][sl] = v[(size_t)(b * S_LEN + s0 + sl) * KVDIM + kvh * DH + d];
    }
    __syncthreads();
#pragma unroll
    for (int r = 0; r < 16; r++) {
        int slot = tid + 256 * r;
        int d  = slot >> 6;
        int sl = slot & 63;
        float x = sm[d][sl];
        __nv_bfloat16 h = __float2bfloat16(x);
        size_t o = ((size_t)((b * NKV + kvh) * DH + d)) * S_LEN + s0 + sl;
        vtH[o] = h;
        vtL[o] = __float2bfloat16(x - __bfloat162float(h));
    }
}

// ---------------- Flash attention on tensor cores (causal, GQA, split bf16) ----------------
#define ATS 72

__global__ void __launch_bounds__(128) attn_mma_kernel(
    const __nv_bfloat16* __restrict__ qH, const __nv_bfloat16* __restrict__ qL,
    const __nv_bfloat16* __restrict__ kH, const __nv_bfloat16* __restrict__ kL,
    const __nv_bfloat16* __restrict__ vH, const __nv_bfloat16* __restrict__ vL,
    __nv_bfloat16* __restrict__ oH, __nv_bfloat16* __restrict__ oL)
{
    __shared__ __nv_bfloat16 sKH[64 * ATS], sKL[64 * ATS];
    __shared__ __nv_bfloat16 sVH[64 * ATS], sVL[64 * ATS];

    const int b   = blockIdx.z;
    const int h   = blockIdx.y;
    const int kvh = h >> 3;
    const int q0  = blockIdx.x * 64;
    const int tid  = threadIdx.x;
    const int w    = tid >> 5;
    const int lane = tid & 31;
    const int fr = lane >> 2;
    const int fc = (lane & 3) * 2;
    const int qrow = q0 + w * 16;

    uint32_t aH[4][4], aL[4][4];
    {
        const __nv_bfloat16* p0 = qH + (size_t)(b * S_LEN + qrow + fr) * HQ + h * DH + fc;
        const __nv_bfloat16* p1 = qL + (size_t)(b * S_LEN + qrow + fr) * HQ + h * DH + fc;
#pragma unroll
        for (int kc = 0; kc < 4; kc++) {
            aH[kc][0] = *(const uint32_t*)(p0 + kc * 16);
            aH[kc][1] = *(const uint32_t*)(p0 + kc * 16 + 8 * HQ);
            aH[kc][2] = *(const uint32_t*)(p0 + kc * 16 + 8);
            aH[kc][3] = *(const uint32_t*)(p0 + kc * 16 + 8 * HQ + 8);
            aL[kc][0] = *(const uint32_t*)(p1 + kc * 16);
            aL[kc][1] = *(const uint32_t*)(p1 + kc * 16 + 8 * HQ);
            aL[kc][2] = *(const uint32_t*)(p1 + kc * 16 + 8);
            aL[kc][3] = *(const uint32_t*)(p1 + kc * 16 + 8 * HQ + 8);
        }
    }

    float oacc[8][4];
#pragma unroll
    for (int nt = 0; nt < 8; nt++)
#pragma unroll
        for (int e = 0; e < 4; e++) oacc[nt][e] = 0.f;
    float mrow0 = -1e30f, mrow1 = -1e30f, lrow0 = 0.f, lrow1 = 0.f;

    const __nv_bfloat16* kHb = kH + (size_t)b * S_LEN * KVDIM + kvh * DH;
    const __nv_bfloat16* kLb = kL + (size_t)b * S_LEN * KVDIM + kvh * DH;
    const __nv_bfloat16* vHb = vH + ((size_t)(b * NKV + kvh) * DH) * S_LEN;
    const __nv_bfloat16* vLb = vL + ((size_t)(b * NKV + kvh) * DH) * S_LEN;

    for (int j0 = 0; j0 <= q0; j0 += 64) {
#pragma unroll
        for (int it = 0; it < 4; it++) {
            int slot = tid + 128 * it;
            int row = slot >> 3;
            int c   = (slot & 7) * 8;
            *(uint4*)&sKH[row * ATS + c] = *(const uint4*)&kHb[(size_t)(j0 + row) * KVDIM + c];
            *(uint4*)&sKL[row * ATS + c] = *(const uint4*)&kLb[(size_t)(j0 + row) * KVDIM + c];
            *(uint4*)&sVH[row * ATS + c] = *(const uint4*)&vHb[(size_t)row * S_LEN + j0 + c];
            *(uint4*)&sVL[row * ATS + c] = *(const uint4*)&vLb[(size_t)row * S_LEN + j0 + c];
        }
        __syncthreads();

        float sc[8][4];
#pragma unroll
        for (int nt = 0; nt < 8; nt++)
#pragma unroll
            for (int e = 0; e < 4; e++) sc[nt][e] = 0.f;

#pragma unroll
        for (int nt = 0; nt < 8; nt++)
#pragma unroll
            for (int kc = 0; kc < 4; kc++) {
                const __nv_bfloat16* kp = &sKH[(nt * 8 + fr) * ATS + kc * 16 + fc];
                uint32_t b0 = *(const uint32_t*)kp, b1 = *(const uint32_t*)(kp + 8);
                MMA_BF16(sc[nt], aH[kc], b0, b1);
                MMA_BF16(sc[nt], aL[kc], b0, b1);
                const __nv_bfloat16* kq = &sKL[(nt * 8 + fr) * ATS + kc * 16 + fc];
                uint32_t c0 = *(const uint32_t*)kq, c1 = *(const uint32_t*)(kq + 8);
                MMA_BF16(sc[nt], aH[kc], c0, c1);
            }

        if (j0 == q0) {
#pragma unroll
            for (int nt = 0; nt < 8; nt++) {
                int col = j0 + nt * 8 + fc;
                int r0 = qrow + fr, r1 = r0 + 8;
                if (col     > r0) sc[nt][0] = -1e30f;
                if (col + 1 > r0) sc[nt][1] = -1e30f;
                if (col     > r1) sc[nt][2] = -1e30f;
                if (col + 1 > r1) sc[nt][3] = -1e30f;
            }
        }

        float mc0 = -1e30f, mc1 = -1e30f;
#pragma unroll
        for (int nt = 0; nt < 8; nt++) {
            mc0 = fmaxf(mc0, fmaxf(sc[nt][0], sc[nt][1]));
            mc1 = fmaxf(mc1, fmaxf(sc[nt][2], sc[nt][3]));
        }
        mc0 = fmaxf(mc0, __shfl_xor_sync(0xffffffffu, mc0, 1));
        mc0 = fmaxf(mc0, __shfl_xor_sync(0xffffffffu, mc0, 2));
        mc1 = fmaxf(mc1, __shfl_xor_sync(0xffffffffu, mc1, 1));
        mc1 = fmaxf(mc1, __shfl_xor_sync(0xffffffffu, mc1, 2));

        float mn0 = fmaxf(mrow0, mc0), mn1 = fmaxf(mrow1, mc1);
        float scale0 = __expf(mrow0 - mn0), scale1 = __expf(mrow1 - mn1);
        mrow0 = mn0; mrow1 = mn1;
#pragma unroll
        for (int nt = 0; nt < 8; nt++) {
            oacc[nt][0] *= scale0; oacc[nt][1] *= scale0;
            oacc[nt][2] *= scale1; oacc[nt][3] *= scale1;
        }
        float rs0 = 0.f, rs1 = 0.f;
#pragma unroll
        for (int nt = 0; nt < 8; nt++) {
            sc[nt][0] = __expf(sc[nt][0] - mn0);
            sc[nt][1] = __expf(sc[nt][1] - mn0);
            sc[nt][2] = __expf(sc[nt][2] - mn1);
            sc[nt][3] = __expf(sc[nt][3] - mn1);
            rs0 += sc[nt][0] + sc[nt][1];
            rs1 += sc[nt][2] + sc[nt][3];
        }
        rs0 += __shfl_xor_sync(0xffffffffu, rs0, 1);
        rs0 += __shfl_xor_sync(0xffffffffu, rs0, 2);
        rs1 += __shfl_xor_sync(0xffffffffu, rs1, 1);
        rs1 += __shfl_xor_sync(0xffffffffu, rs1, 2);
        lrow0 = lrow0 * scale0 + rs0;
        lrow1 = lrow1 * scale1 + rs1;

#pragma unroll
        for (int kc = 0; kc < 4; kc++) {
            uint32_t ph[4], pl[4];
            split2(sc[2 * kc][0],     sc[2 * kc][1],     ph[0], pl[0]);
            split2(sc[2 * kc][2],     sc[2 * kc][3],     ph[1], pl[1]);
            split2(sc[2 * kc + 1][0], sc[2 * kc + 1][1], ph[2], pl[2]);
            split2(sc[2 * kc + 1][2], sc[2 * kc + 1][3], ph[3], pl[3]);
#pragma unroll
            for (int nt = 0; nt < 8; nt++) {
                const __nv_bfloat16* vp = &sVH[(nt * 8 + fr) * ATS + kc * 16 + fc];
                uint32_t b0 = *(const uint32_t*)vp, b1 = *(const uint32_t*)(vp + 8);
                MMA_BF16(oacc[nt], ph, b0, b1);
                MMA_BF16(oacc[nt], pl, b0, b1);
                const __nv_bfloat16* vq = &sVL[(nt * 8 + fr) * ATS + kc * 16 + fc];
                uint32_t c0 = *(const uint32_t*)vq, c1 = *(const uint32_t*)(vq + 8);
                MMA_BF16(oacc[nt], ph, c0, c1);
            }
        }
        __syncthreads();
    }

    float inv0 = 1.f / lrow0, inv1 = 1.f / lrow1;
    size_t o0 = (size_t)(b * S_LEN + qrow + fr) * HQ + h * DH + fc;
#pragma unroll
    for (int nt = 0; nt < 8; nt++) {
        uint32_t h0, l0, h1, l1;
        split2(oacc[nt][0] * inv0, oacc[nt][1] * inv0, h0, l0);
        split2(oacc[nt][2] * inv1, oacc[nt][3] * inv1, h1, l1);
        *(uint32_t*)&oH[o0 + nt * 8]          = h0;
        *(uint32_t*)&oL[o0 + nt * 8]          = l0;
        *(uint32_t*)&oH[o0 + 8 * HQ + nt * 8] = h1;
        *(uint32_t*)&oL[o0 + 8 * HQ + nt * 8] = l1;
    }
}

// ---------------- launch ----------------
extern "C" void kernel_launch(void* const* d_in, const int* in_sizes, int n_in,
                              void* d_out, int out_size)
{
    const float* hs   = (const float*)d_in[0];
    const float* cosb = (const float*)d_in[3];
    const float* sinb = (const float*)d_in[4];
    const float* wq   = (const float*)d_in[5];
    const float* wk   = (const float*)d_in[6];
    const float* wv   = (const float*)d_in[7];
    const float* wd   = (const float*)d_in[8];
    float* out = (float*)d_out;

    float *pq, *pk, *pv;
    __nv_bfloat16 *hsH, *hsL, *aoH, *aoL, *qsH, *qsL, *ksH, *ksL, *vtH, *vtL;
    __nv_bfloat16 *wqH, *wqL, *wdH, *wdL, *wkH, *wkL, *wvH, *wvL;
    cudaGetSymbolAddress((void**)&pq,  g_q);
    cudaGetSymbolAddress((void**)&pk,  g_k);
    cudaGetSymbolAddress((void**)&pv,  g_v);
    cudaGetSymbolAddress((void**)&hsH, g_hsH); cudaGetSymbolAddress((void**)&hsL, g_hsL);
    cudaGetSymbolAddress((void**)&aoH, g_aoH); cudaGetSymbolAddress((void**)&aoL, g_aoL);
    cudaGetSymbolAddress((void**)&qsH, g_qsH); cudaGetSymbolAddress((void**)&qsL, g_qsL);
    cudaGetSymbolAddress((void**)&ksH, g_ksH); cudaGetSymbolAddress((void**)&ksL, g_ksL);
    cudaGetSymbolAddress((void**)&vtH, g_vtH); cudaGetSymbolAddress((void**)&vtL, g_vtL);
    cudaGetSymbolAddress((void**)&wqH, g_wqH); cudaGetSymbolAddress((void**)&wqL, g_wqL);
    cudaGetSymbolAddress((void**)&wdH, g_wdH); cudaGetSymbolAddress((void**)&wdL, g_wdL);
    cudaGetSymbolAddress((void**)&wkH, g_wkH); cudaGetSymbolAddress((void**)&wkL, g_wkL);
    cudaGetSymbolAddress((void**)&wvH, g_wvH); cudaGetSymbolAddress((void**)&wvL, g_wvL);

    static cudaStream_t st1 = nullptr, st2 = nullptr;
    static cudaEvent_t evRoot, evHs, evKV, evWd;
    if (!st1) {
        cudaStreamCreateWithFlags(&st1, cudaStreamNonBlocking);
        cudaStreamCreateWithFlags(&st2, cudaStreamNonBlocking);
        cudaEventCreateWithFlags(&evRoot, cudaEventDisableTiming);
        cudaEventCreateWithFlags(&evHs,   cudaEventDisableTiming);
        cudaEventCreateWithFlags(&evKV,   cudaEventDisableTiming);
        cudaEventCreateWithFlags(&evWd,   cudaEventDisableTiming);
        cudaFuncSetAttribute(gemm3_kernel,
                             cudaFuncAttributeMaxDynamicSharedMemorySize, GEMM_SMEM);
        cudaFuncSetAttribute(gemm3_kv_kernel,
                             cudaFuncAttributeMaxDynamicSharedMemorySize, GEMM_SMEM);
    }

    // fork side streams off the capture-origin stream
    cudaEventRecord(evRoot, 0);
    cudaStreamWaitEvent(st1, evRoot, 0);
    cudaStreamWaitEvent(st2, evRoot, 0);

    // ---- stream 0 (critical path): hs split -> Q gemm -> rope_q ----
    {
        int n4 = MROWS * HQ / 4;
        split_kernel<<<(n4 + 255) / 256, 256>>>(hs, hsH, hsL, n4);
        cudaEventRecord(evHs, 0);
        n4 = HQ * HQ / 4;
        split_kernel<<<(n4 + 255) / 256, 256>>>(wq, wqH, wqL, n4);
    }
    gemm3_kernel<<<dim3(HQ / GBN, MROWS / GBM), 256, GEMM_SMEM>>>(hsH, hsL, wqH, wqL, pq, HQ, HQ);
    {
        int tq = MROWS * NH * (DH / 2);
        rope_split_kernel<<<(tq + 255) / 256, 256>>>(pq, cosb, sinb, qsH, qsL, NH, 0.125f);
    }

    // ---- stream 1: wk/wv splits -> fused KV gemm -> rope_k + V transpose ----
    {
        int n4 = KVDIM * HQ / 4;
        split_kernel<<<(n4 + 255) / 256, 256, 0, st1>>>(wk, wkH, wkL, n4);
        split_kernel<<<(n4 + 255) / 256, 256, 0, st1>>>(wv, wvH, wvL, n4);
        cudaStreamWaitEvent(st1, evHs, 0);
        gemm3_kv_kernel<<<dim3(8, MROWS / GBM), 256, GEMM_SMEM, st1>>>(
            hsH, hsL, wkH, wkL, wvH, wvL, pk, pv);
        int tk = MROWS * NKV * (DH / 2);
        rope_split_kernel<<<(tk + 255) / 256, 256, 0, st1>>>(pk, cosb, sinb, ksH, ksL, NKV, 1.0f);
        splitvt_kernel<<<dim3(S_LEN / 64, NKV, BDIM), 256, 0, st1>>>(pv, vtH, vtL);
        cudaEventRecord(evKV, st1);
    }

    // ---- stream 2: wd split (needed only by out-proj) ----
    {
        int n4 = HQ * HQ / 4;
        split_kernel<<<(n4 + 255) / 256, 256, 0, st2>>>(wd, wdH, wdL, n4);
        cudaEventRecord(evWd, st2);
    }

    // ---- join: attention, then out-proj ----
    cudaStreamWaitEvent(0, evKV, 0);
    attn_mma_kernel<<<dim3(S_LEN / 64, NH, BDIM), 128>>>(qsH, qsL, ksH, ksL, vtH, vtL, aoH, aoL);
    cudaStreamWaitEvent(0, evWd, 0);
    gemm3_kernel<<<dim3(HQ / GBN, MROWS / GBM), 256, GEMM_SMEM>>>(aoH, aoL, wdH, wdL, out, HQ, HQ);
}

// round 12
// speedup vs baseline: 3.8627x; 1.1155x over previous
#include <cuda_runtime.h>
#include <cuda_bf16.h>
#include <cstdint>

#define S_LEN 1024
#define BDIM  2
#define HQ    4096
#define NKV   8
#define NH    64
#define DH    64
#define MROWS (BDIM * S_LEN)   // 2048
#define KVDIM (NKV * DH)       // 512

// ---------------- scratch (device globals; no allocs allowed) ----------------
__device__ float g_q [MROWS * HQ];
__device__ float g_k [MROWS * KVDIM];
__device__ float g_v [MROWS * KVDIM];
__device__ __nv_bfloat16 g_hsH[MROWS * HQ], g_hsL[MROWS * HQ];
__device__ __nv_bfloat16 g_aoH[MROWS * HQ], g_aoL[MROWS * HQ];
__device__ __nv_bfloat16 g_qsH[MROWS * HQ], g_qsL[MROWS * HQ];
__device__ __nv_bfloat16 g_ksH[MROWS * KVDIM], g_ksL[MROWS * KVDIM];
__device__ __nv_bfloat16 g_vtH[MROWS * KVDIM], g_vtL[MROWS * KVDIM];
__device__ __nv_bfloat16 g_wqH[HQ * HQ],    g_wqL[HQ * HQ];
__device__ __nv_bfloat16 g_wdH[HQ * HQ],    g_wdL[HQ * HQ];
__device__ __nv_bfloat16 g_wkH[KVDIM * HQ], g_wkL[KVDIM * HQ];
__device__ __nv_bfloat16 g_wvH[KVDIM * HQ], g_wvL[KVDIM * HQ];

// ---------------- helpers ----------------
__device__ __forceinline__ void split2(float x, float y, uint32_t& hi, uint32_t& lo)
{
    __nv_bfloat16 hx = __float2bfloat16(x), hy = __float2bfloat16(y);
    __nv_bfloat16 lx = __float2bfloat16(x - __bfloat162float(hx));
    __nv_bfloat16 ly = __float2bfloat16(y - __bfloat162float(hy));
    __nv_bfloat162 H = __halves2bfloat162(hx, hy);
    __nv_bfloat162 L = __halves2bfloat162(lx, ly);
    hi = *(uint32_t*)&H; lo = *(uint32_t*)&L;
}

#define MMA_BF16(d, av, b0, b1) \
    asm volatile("mma.sync.aligned.m16n8k16.row.col.f32.bf16.bf16.f32 " \
                 "{%0,%1,%2,%3}, {%4,%5,%6,%7}, {%8,%9}, {%0,%1,%2,%3};\n" \
                 : "+f"(d[0]), "+f"(d[1]), "+f"(d[2]), "+f"(d[3]) \
                 : "r"(av[0]), "r"(av[1]), "r"(av[2]), "r"(av[3]), \
                   "r"(b0), "r"(b1))

#define LDSM4(d0, d1, d2, d3, a) \
    asm volatile("ldmatrix.sync.aligned.m8n8.x4.shared.b16 {%0,%1,%2,%3}, [%4];\n" \
                 : "=r"(d0), "=r"(d1), "=r"(d2), "=r"(d3) : "r"(a))

__device__ __forceinline__ void cp16(uint32_t sa, const void* g)
{
    asm volatile("cp.async.cg.shared.global [%0], [%1], 16;\n" :: "r"(sa), "l"(g));
}
#define CP_COMMIT() asm volatile("cp.async.commit_group;\n" ::: "memory")
#define CP_WAIT1()  asm volatile("cp.async.wait_group 1;\n" ::: "memory")

// ---------------- fp32 -> (hi, lo) bf16 split ----------------
__global__ void __launch_bounds__(256) split_kernel(
    const float* __restrict__ x, __nv_bfloat16* __restrict__ hi,
    __nv_bfloat16* __restrict__ lo, int n4)
{
    int i = blockIdx.x * blockDim.x + threadIdx.x;
    if (i >= n4) return;
    float4 v = ((const float4*)x)[i];
    uint32_t h0, l0, h1, l1;
    split2(v.x, v.y, h0, l0);
    split2(v.z, v.w, h1, l1);
    uint32_t* hp = (uint32_t*)hi + (size_t)i * 2;
    uint32_t* lp = (uint32_t*)lo + (size_t)i * 2;
    hp[0] = h0; hp[1] = h1;
    lp[0] = l0; lp[1] = l1;
}

// ---------------- bf16 split-GEMM, cp.async double-buffered, ldmatrix ----------------
// C[m,n] = sum_k A[m,k]*W[n,k];  C = Ah*Bh + Al*Bh + Ah*Bl  (fp32 accum)
#define GBM 128
#define GBN 128
#define GBK 32
#define ASTR 40
#define GTILE (GBM * ASTR)            // elements per array per stage
#define GEMM_SMEM (2 * 4 * GTILE * 2) // bytes

__device__ __forceinline__ void gemm3_body(
    const __nv_bfloat16* __restrict__ AH, const __nv_bfloat16* __restrict__ AL,
    const __nv_bfloat16* __restrict__ BH, const __nv_bfloat16* __restrict__ BL,
    float* __restrict__ C, int K, int N, int m0, int n0, __nv_bfloat16* smem)
{
    const int tid  = threadIdx.x;
    const int wid  = tid >> 5;
    const int lane = tid & 31;
    const int wm = (wid & 1) * 64;
    const int wn = (wid >> 1) * 32;
    const int fr = lane >> 2;
    const int fc = (lane & 3) * 2;

    float acc[4][4][4];
#pragma unroll
    for (int mt = 0; mt < 4; mt++)
#pragma unroll
        for (int nt = 0; nt < 4; nt++)
#pragma unroll
            for (int e = 0; e < 4; e++) acc[mt][nt][e] = 0.f;

    // ldmatrix per-lane byte offsets within one array
    int offA[4], offB[2];
#pragma unroll
    for (int mt = 0; mt < 4; mt++)
        offA[mt] = ((wm + mt * 16 + (lane & 7) + ((lane >> 3) & 1) * 8) * ASTR
                    + (lane >> 4) * 8) * 2;
#pragma unroll
    for (int p = 0; p < 2; p++)
        offB[p] = ((wn + p * 16 + (lane >> 4) * 8 + (lane & 7)) * ASTR
                   + ((lane >> 3) & 1) * 8) * 2;

    const uint32_t su = (uint32_t)__cvta_generic_to_shared(smem);

    auto load_stage = [&](int s, int k0) {
        __nv_bfloat16* base = smem + s * 4 * GTILE;
#pragma unroll
        for (int r = 0; r < 2; r++) {
            int slot = tid + 256 * r;
            int row  = slot >> 2;
            int q    = (slot & 3) * 8;
            size_t ga = (size_t)(m0 + row) * K + k0 + q;
            size_t gb = (size_t)(n0 + row) * K + k0 + q;
            uint32_t da = (uint32_t)__cvta_generic_to_shared(base + row * ASTR + q);
            cp16(da,             AH + ga);
            cp16(da + 2*GTILE,   AL + ga);
            cp16(da + 4*GTILE,   BH + gb);
            cp16(da + 6*GTILE,   BL + gb);
        }
    };

    load_stage(0, 0);
    CP_COMMIT();

    int s = 0;
    for (int k0 = 0; k0 < K; k0 += GBK) {
        if (k0 + GBK < K) load_stage(s ^ 1, k0 + GBK);
        CP_COMMIT();
        CP_WAIT1();
        __syncthreads();

        uint32_t sb  = su + s * (4 * GTILE * 2);
        uint32_t aAH = sb,              aAL = sb + 2 * GTILE;
        uint32_t aBH = sb + 4 * GTILE,  aBL = sb + 6 * GTILE;

#pragma unroll
        for (int kk = 0; kk < GBK; kk += 16) {
            uint32_t bh[4][2], bl[4][2];
            LDSM4(bh[0][0], bh[0][1], bh[1][0], bh[1][1], aBH + offB[0] + kk * 2);
            LDSM4(bh[2][0], bh[2][1], bh[3][0], bh[3][1], aBH + offB[1] + kk * 2);
            LDSM4(bl[0][0], bl[0][1], bl[1][0], bl[1][1], aBL + offB[0] + kk * 2);
            LDSM4(bl[2][0], bl[2][1], bl[3][0], bl[3][1], aBL + offB[1] + kk * 2);
            uint32_t a[4][4];
#pragma unroll
            for (int mt = 0; mt < 4; mt++)
                LDSM4(a[mt][0], a[mt][1], a[mt][2], a[mt][3], aAH + offA[mt] + kk * 2);
#pragma unroll
            for (int mt = 0; mt < 4; mt++)
#pragma unroll
                for (int nt = 0; nt < 4; nt++) {
                    MMA_BF16(acc[mt][nt], a[mt], bh[nt][0], bh[nt][1]);
                    MMA_BF16(acc[mt][nt], a[mt], bl[nt][0], bl[nt][1]);
                }
#pragma unroll
            for (int mt = 0; mt < 4; mt++)
                LDSM4(a[mt][0], a[mt][1], a[mt][2], a[mt][3], aAL + offA[mt] + kk * 2);
#pragma unroll
            for (int mt = 0; mt < 4; mt++)
#pragma unroll
                for (int nt = 0; nt < 4; nt++)
                    MMA_BF16(acc[mt][nt], a[mt], bh[nt][0], bh[nt][1]);
        }
        __syncthreads();
        s ^= 1;
    }

#pragma unroll
    for (int mt = 0; mt < 4; mt++)
#pragma unroll
        for (int nt = 0; nt < 4; nt++) {
            size_t base = (size_t)(m0 + wm + mt * 16 + fr) * N + n0 + wn + nt * 8 + fc;
            *(float2*)&C[base]                 = make_float2(acc[mt][nt][0], acc[mt][nt][1]);
            *(float2*)&C[base + 8 * (size_t)N] = make_float2(acc[mt][nt][2], acc[mt][nt][3]);
        }
}

__global__ void __launch_bounds__(256, 2) gemm3_kernel(
    const __nv_bfloat16* __restrict__ AH, const __nv_bfloat16* __restrict__ AL,
    const __nv_bfloat16* __restrict__ BH, const __nv_bfloat16* __restrict__ BL,
    float* __restrict__ C, int K, int N)
{
    extern __shared__ __nv_bfloat16 smem[];
    gemm3_body(AH, AL, BH, BL, C, K, N, blockIdx.y * GBM, blockIdx.x * GBN, smem);
}

// fused K+V projection: grid.x = 8; 0..3 -> K, 4..7 -> V
__global__ void __launch_bounds__(256, 2) gemm3_kv_kernel(
    const __nv_bfloat16* __restrict__ AH, const __nv_bfloat16* __restrict__ AL,
    const __nv_bfloat16* __restrict__ KH, const __nv_bfloat16* __restrict__ KL,
    const __nv_bfloat16* __restrict__ VH, const __nv_bfloat16* __restrict__ VL,
    float* __restrict__ Ck, float* __restrict__ Cv)
{
    extern __shared__ __nv_bfloat16 smem[];
    const __nv_bfloat16 *BH, *BL;
    float* C;
    int n0;
    if (blockIdx.x < 4) { BH = KH; BL = KL; C = Ck; n0 = blockIdx.x * GBN; }
    else                { BH = VH; BL = VL; C = Cv; n0 = (blockIdx.x - 4) * GBN; }
    gemm3_body(AH, AL, BH, BL, C, HQ, KVDIM, blockIdx.y * GBM, n0, smem);
}

// ---------------- RoPE + hi/lo split ----------------
__global__ void rope_split_kernel(
    const float* __restrict__ p, const float* __restrict__ cosb,
    const float* __restrict__ sinb, __nv_bfloat16* __restrict__ outH,
    __nv_bfloat16* __restrict__ outL, int nheads, float scl)
{
    int idx = blockIdx.x * blockDim.x + threadIdx.x;
    int total = MROWS * nheads * (DH / 2);
    if (idx >= total) return;
    int d  = idx & 31;
    int h  = (idx >> 5) % nheads;
    int bs = idx / (nheads * 32);
    int s  = bs & (S_LEN - 1);
    size_t base = (size_t)bs * nheads * DH + h * DH;
    float x1 = p[base + d];
    float x2 = p[base + d + 32];
    float c1 = cosb[s * DH + d],      s1 = sinb[s * DH + d];
    float c2 = cosb[s * DH + d + 32], s2 = sinb[s * DH + d + 32];
    float y1 = (x1 * c1 - x2 * s1) * scl;
    float y2 = (x2 * c2 + x1 * s2) * scl;
    __nv_bfloat16 h1 = __float2bfloat16(y1);
    __nv_bfloat16 h2 = __float2bfloat16(y2);
    outH[base + d]      = h1;
    outH[base + d + 32] = h2;
    outL[base + d]      = __float2bfloat16(y1 - __bfloat162float(h1));
    outL[base + d + 32] = __float2bfloat16(y2 - __bfloat162float(h2));
}

// ---------------- V split + transpose ----------------
__global__ void __launch_bounds__(256) splitvt_kernel(
    const float* __restrict__ v, __nv_bfloat16* __restrict__ vtH,
    __nv_bfloat16* __restrict__ vtL)
{
    __shared__ float sm[64][65];
    const int s0  = blockIdx.x * 64;
    const int kvh = blockIdx.y;
    const int b   = blockIdx.z;
    const int tid = threadIdx.x;

#pragma unroll
    for (int r = 0; r < 16; r++) {
        int slot = tid + 256 * r;
        int sl = slot >> 6;
        int d  = slot & 63;
        sm[d][sl] = v[(size_t)(b * S_LEN + s0 + sl) * KVDIM + kvh * DH + d];
    }
    __syncthreads();
#pragma unroll
    for (int r = 0; r < 16; r++) {
        int slot = tid + 256 * r;
        int d  = slot >> 6;
        int sl = slot & 63;
        float x = sm[d][sl];
        __nv_bfloat16 h = __float2bfloat16(x);
        size_t o = ((size_t)((b * NKV + kvh) * DH + d)) * S_LEN + s0 + sl;
        vtH[o] = h;
        vtL[o] = __float2bfloat16(x - __bfloat162float(h));
    }
}

// ---------------- Flash attention: tensor cores + cp.async pipeline + ldmatrix ----------------
#define ATS 72
#define ATILE (64 * ATS)               // elements per array per stage
#define ATT_SMEM (2 * 4 * ATILE * 2)   // bytes

__global__ void __launch_bounds__(128) attn_mma_kernel(
    const __nv_bfloat16* __restrict__ qH, const __nv_bfloat16* __restrict__ qL,
    const __nv_bfloat16* __restrict__ kH, const __nv_bfloat16* __restrict__ kL,
    const __nv_bfloat16* __restrict__ vH, const __nv_bfloat16* __restrict__ vL,
    __nv_bfloat16* __restrict__ oH, __nv_bfloat16* __restrict__ oL)
{
    extern __shared__ __nv_bfloat16 smem[];

    const int b   = blockIdx.z;
    const int h   = blockIdx.y;
    const int kvh = h >> 3;
    const int q0  = blockIdx.x * 64;
    const int tid  = threadIdx.x;
    const int w    = tid >> 5;
    const int lane = tid & 31;
    const int fr = lane >> 2;
    const int fc = (lane & 3) * 2;
    const int qrow = q0 + w * 16;

    // ldmatrix per-lane byte offsets (B-operand layout, pairs of 8-row tiles)
    int offK[4];
#pragma unroll
    for (int p = 0; p < 4; p++)
        offK[p] = ((p * 16 + (lane >> 4) * 8 + (lane & 7)) * ATS
                   + ((lane >> 3) & 1) * 8) * 2;

    const uint32_t su = (uint32_t)__cvta_generic_to_shared(smem);

    // Q fragments (hi/lo)
    uint32_t aH[4][4], aL[4][4];
    {
        const __nv_bfloat16* p0 = qH + (size_t)(b * S_LEN + qrow + fr) * HQ + h * DH + fc;
        const __nv_bfloat16* p1 = qL + (size_t)(b * S_LEN + qrow + fr) * HQ + h * DH + fc;
#pragma unroll
        for (int kc = 0; kc < 4; kc++) {
            aH[kc][0] = *(const uint32_t*)(p0 + kc * 16);
            aH[kc][1] = *(const uint32_t*)(p0 + kc * 16 + 8 * HQ);
            aH[kc][2] = *(const uint32_t*)(p0 + kc * 16 + 8);
            aH[kc][3] = *(const uint32_t*)(p0 + kc * 16 + 8 * HQ + 8);
            aL[kc][0] = *(const uint32_t*)(p1 + kc * 16);
            aL[kc][1] = *(const uint32_t*)(p1 + kc * 16 + 8 * HQ);
            aL[kc][2] = *(const uint32_t*)(p1 + kc * 16 + 8);
            aL[kc][3] = *(const uint32_t*)(p1 + kc * 16 + 8 * HQ + 8);
        }
    }

    float oacc[8][4];
#pragma unroll
    for (int nt = 0; nt < 8; nt++)
#pragma unroll
        for (int e = 0; e < 4; e++) oacc[nt][e] = 0.f;
    float mrow0 = -1e30f, mrow1 = -1e30f, lrow0 = 0.f, lrow1 = 0.f;

    const __nv_bfloat16* kHb = kH + (size_t)b * S_LEN * KVDIM + kvh * DH;
    const __nv_bfloat16* kLb = kL + (size_t)b * S_LEN * KVDIM + kvh * DH;
    const __nv_bfloat16* vHb = vH + ((size_t)(b * NKV + kvh) * DH) * S_LEN;
    const __nv_bfloat16* vLb = vL + ((size_t)(b * NKV + kvh) * DH) * S_LEN;

    auto load_tile = [&](int s, int j0) {
        __nv_bfloat16* base = smem + s * 4 * ATILE;
#pragma unroll
        for (int it = 0; it < 4; it++) {
            int slot = tid + 128 * it;
            int row = slot >> 3;
            int c   = (slot & 7) * 8;
            uint32_t da = (uint32_t)__cvta_generic_to_shared(base + row * ATS + c);
            cp16(da,             &kHb[(size_t)(j0 + row) * KVDIM + c]);
            cp16(da + 2*ATILE,   &kLb[(size_t)(j0 + row) * KVDIM + c]);
            cp16(da + 4*ATILE,   &vHb[(size_t)row * S_LEN + j0 + c]);
            cp16(da + 6*ATILE,   &vLb[(size_t)row * S_LEN + j0 + c]);
        }
    };

    load_tile(0, 0);
    CP_COMMIT();

    int s = 0;
    for (int j0 = 0; j0 <= q0; j0 += 64) {
        if (j0 + 64 <= q0) load_tile(s ^ 1, j0 + 64);
        CP_COMMIT();
        CP_WAIT1();
        __syncthreads();

        uint32_t sb  = su + s * (4 * ATILE * 2);
        uint32_t aKH = sb,              aKL = sb + 2 * ATILE;
        uint32_t aVH = sb + 4 * ATILE,  aVL = sb + 6 * ATILE;

        // ---- scores: S = Qh*Kh + Ql*Kh + Qh*Kl ----
        float sc[8][4];
#pragma unroll
        for (int nt = 0; nt < 8; nt++)
#pragma unroll
            for (int e = 0; e < 4; e++) sc[nt][e] = 0.f;

#pragma unroll
        for (int kc = 0; kc < 4; kc++)
#pragma unroll
            for (int p = 0; p < 4; p++) {
                uint32_t b00, b01, b10, b11;
                LDSM4(b00, b01, b10, b11, aKH + offK[p] + kc * 32);
                MMA_BF16(sc[2*p],     aH[kc], b00, b01);
                MMA_BF16(sc[2*p],     aL[kc], b00, b01);
                MMA_BF16(sc[2*p + 1], aH[kc], b10, b11);
                MMA_BF16(sc[2*p + 1], aL[kc], b10, b11);
                uint32_t c00, c01, c10, c11;
                LDSM4(c00, c01, c10, c11, aKL + offK[p] + kc * 32);
                MMA_BF16(sc[2*p],     aH[kc], c00, c01);
                MMA_BF16(sc[2*p + 1], aH[kc], c10, c11);
            }

        if (j0 == q0) {
#pragma unroll
            for (int nt = 0; nt < 8; nt++) {
                int col = j0 + nt * 8 + fc;
                int r0 = qrow + fr, r1 = r0 + 8;
                if (col     > r0) sc[nt][0] = -1e30f;
                if (col + 1 > r0) sc[nt][1] = -1e30f;
                if (col     > r1) sc[nt][2] = -1e30f;
                if (col + 1 > r1) sc[nt][3] = -1e30f;
            }
        }

        // ---- online softmax (rows fr and fr+8) ----
        float mc0 = -1e30f, mc1 = -1e30f;
#pragma unroll
        for (int nt = 0; nt < 8; nt++) {
            mc0 = fmaxf(mc0, fmaxf(sc[nt][0], sc[nt][1]));
            mc1 = fmaxf(mc1, fmaxf(sc[nt][2], sc[nt][3]));
        }
        mc0 = fmaxf(mc0, __shfl_xor_sync(0xffffffffu, mc0, 1));
        mc0 = fmaxf(mc0, __shfl_xor_sync(0xffffffffu, mc0, 2));
        mc1 = fmaxf(mc1, __shfl_xor_sync(0xffffffffu, mc1, 1));
        mc1 = fmaxf(mc1, __shfl_xor_sync(0xffffffffu, mc1, 2));

        float mn0 = fmaxf(mrow0, mc0), mn1 = fmaxf(mrow1, mc1);
        float scale0 = __expf(mrow0 - mn0), scale1 = __expf(mrow1 - mn1);
        mrow0 = mn0; mrow1 = mn1;
#pragma unroll
        for (int nt = 0; nt < 8; nt++) {
            oacc[nt][0] *= scale0; oacc[nt][1] *= scale0;
            oacc[nt][2] *= scale1; oacc[nt][3] *= scale1;
        }
        float rs0 = 0.f, rs1 = 0.f;
#pragma unroll
        for (int nt = 0; nt < 8; nt++) {
            sc[nt][0] = __expf(sc[nt][0] - mn0);
            sc[nt][1] = __expf(sc[nt][1] - mn0);
            sc[nt][2] = __expf(sc[nt][2] - mn1);
            sc[nt][3] = __expf(sc[nt][3] - mn1);
            rs0 += sc[nt][0] + sc[nt][1];
            rs1 += sc[nt][2] + sc[nt][3];
        }
        rs0 += __shfl_xor_sync(0xffffffffu, rs0, 1);
        rs0 += __shfl_xor_sync(0xffffffffu, rs0, 2);
        rs1 += __shfl_xor_sync(0xffffffffu, rs1, 1);
        rs1 += __shfl_xor_sync(0xffffffffu, rs1, 2);
        lrow0 = lrow0 * scale0 + rs0;
        lrow1 = lrow1 * scale1 + rs1;

        // ---- O += Ph*Vh + Pl*Vh + Ph*Vl ----
#pragma unroll
        for (int kc = 0; kc < 4; kc++) {
            uint32_t ph[4], pl[4];
            split2(sc[2 * kc][0],     sc[2 * kc][1],     ph[0], pl[0]);
            split2(sc[2 * kc][2],     sc[2 * kc][3],     ph[1], pl[1]);
            split2(sc[2 * kc + 1][0], sc[2 * kc + 1][1], ph[2], pl[2]);
            split2(sc[2 * kc + 1][2], sc[2 * kc + 1][3], ph[3], pl[3]);
#pragma unroll
            for (int p = 0; p < 4; p++) {
                uint32_t b00, b01, b10, b11;
                LDSM4(b00, b01, b10, b11, aVH + offK[p] + kc * 32);
                MMA_BF16(oacc[2*p],     ph, b00, b01);
                MMA_BF16(oacc[2*p],     pl, b00, b01);
                MMA_BF16(oacc[2*p + 1], ph, b10, b11);
                MMA_BF16(oacc[2*p + 1], pl, b10, b11);
                uint32_t c00, c01, c10, c11;
                LDSM4(c00, c01, c10, c11, aVL + offK[p] + kc * 32);
                MMA_BF16(oacc[2*p],     ph, c00, c01);
                MMA_BF16(oacc[2*p + 1], ph, c10, c11);
            }
        }
        __syncthreads();
        s ^= 1;
    }

    float inv0 = 1.f / lrow0, inv1 = 1.f / lrow1;
    size_t o0 = (size_t)(b * S_LEN + qrow + fr) * HQ + h * DH + fc;
#pragma unroll
    for (int nt = 0; nt < 8; nt++) {
        uint32_t h0, l0, h1, l1;
        split2(oacc[nt][0] * inv0, oacc[nt][1] * inv0, h0, l0);
        split2(oacc[nt][2] * inv1, oacc[nt][3] * inv1, h1, l1);
        *(uint32_t*)&oH[o0 + nt * 8]          = h0;
        *(uint32_t*)&oL[o0 + nt * 8]          = l0;
        *(uint32_t*)&oH[o0 + 8 * HQ + nt * 8] = h1;
        *(uint32_t*)&oL[o0 + 8 * HQ + nt * 8] = l1;
    }
}

// ---------------- launch ----------------
extern "C" void kernel_launch(void* const* d_in, const int* in_sizes, int n_in,
                              void* d_out, int out_size)
{
    const float* hs   = (const float*)d_in[0];
    const float* cosb = (const float*)d_in[3];
    const float* sinb = (const float*)d_in[4];
    const float* wq   = (const float*)d_in[5];
    const float* wk   = (const float*)d_in[6];
    const float* wv   = (const float*)d_in[7];
    const float* wd   = (const float*)d_in[8];
    float* out = (float*)d_out;

    float *pq, *pk, *pv;
    __nv_bfloat16 *hsH, *hsL, *aoH, *aoL, *qsH, *qsL, *ksH, *ksL, *vtH, *vtL;
    __nv_bfloat16 *wqH, *wqL, *wdH, *wdL, *wkH, *wkL, *wvH, *wvL;
    cudaGetSymbolAddress((void**)&pq,  g_q);
    cudaGetSymbolAddress((void**)&pk,  g_k);
    cudaGetSymbolAddress((void**)&pv,  g_v);
    cudaGetSymbolAddress((void**)&hsH, g_hsH); cudaGetSymbolAddress((void**)&hsL, g_hsL);
    cudaGetSymbolAddress((void**)&aoH, g_aoH); cudaGetSymbolAddress((void**)&aoL, g_aoL);
    cudaGetSymbolAddress((void**)&qsH, g_qsH); cudaGetSymbolAddress((void**)&qsL, g_qsL);
    cudaGetSymbolAddress((void**)&ksH, g_ksH); cudaGetSymbolAddress((void**)&ksL, g_ksL);
    cudaGetSymbolAddress((void**)&vtH, g_vtH); cudaGetSymbolAddress((void**)&vtL, g_vtL);
    cudaGetSymbolAddress((void**)&wqH, g_wqH); cudaGetSymbolAddress((void**)&wqL, g_wqL);
    cudaGetSymbolAddress((void**)&wdH, g_wdH); cudaGetSymbolAddress((void**)&wdL, g_wdL);
    cudaGetSymbolAddress((void**)&wkH, g_wkH); cudaGetSymbolAddress((void**)&wkL, g_wkL);
    cudaGetSymbolAddress((void**)&wvH, g_wvH); cudaGetSymbolAddress((void**)&wvL, g_wvL);

    static cudaStream_t st1 = nullptr, st2 = nullptr;
    static cudaEvent_t evRoot, evHs, evKV, evWd;
    if (!st1) {
        cudaStreamCreateWithFlags(&st1, cudaStreamNonBlocking);
        cudaStreamCreateWithFlags(&st2, cudaStreamNonBlocking);
        cudaEventCreateWithFlags(&evRoot, cudaEventDisableTiming);
        cudaEventCreateWithFlags(&evHs,   cudaEventDisableTiming);
        cudaEventCreateWithFlags(&evKV,   cudaEventDisableTiming);
        cudaEventCreateWithFlags(&evWd,   cudaEventDisableTiming);
        cudaFuncSetAttribute(gemm3_kernel,
                             cudaFuncAttributeMaxDynamicSharedMemorySize, GEMM_SMEM);
        cudaFuncSetAttribute(gemm3_kv_kernel,
                             cudaFuncAttributeMaxDynamicSharedMemorySize, GEMM_SMEM);
        cudaFuncSetAttribute(attn_mma_kernel,
                             cudaFuncAttributeMaxDynamicSharedMemorySize, ATT_SMEM);
    }

    // fork side streams off the capture-origin stream
    cudaEventRecord(evRoot, 0);
    cudaStreamWaitEvent(st1, evRoot, 0);
    cudaStreamWaitEvent(st2, evRoot, 0);

    // ---- stream 0 (critical path): hs split -> Q gemm -> rope_q ----
    {
        int n4 = MROWS * HQ / 4;
        split_kernel<<<(n4 + 255) / 256, 256>>>(hs, hsH, hsL, n4);
        cudaEventRecord(evHs, 0);
        n4 = HQ * HQ / 4;
        split_kernel<<<(n4 + 255) / 256, 256>>>(wq, wqH, wqL, n4);
    }
    gemm3_kernel<<<dim3(HQ / GBN, MROWS / GBM), 256, GEMM_SMEM>>>(hsH, hsL, wqH, wqL, pq, HQ, HQ);
    {
        int tq = MROWS * NH * (DH / 2);
        rope_split_kernel<<<(tq + 255) / 256, 256>>>(pq, cosb, sinb, qsH, qsL, NH, 0.125f);
    }

    // ---- stream 1: wk/wv splits -> fused KV gemm -> rope_k + V transpose ----
    {
        int n4 = KVDIM * HQ / 4;
        split_kernel<<<(n4 + 255) / 256, 256, 0, st1>>>(wk, wkH, wkL, n4);
        split_kernel<<<(n4 + 255) / 256, 256, 0, st1>>>(wv, wvH, wvL, n4);
        cudaStreamWaitEvent(st1, evHs, 0);
        gemm3_kv_kernel<<<dim3(8, MROWS / GBM), 256, GEMM_SMEM, st1>>>(
            hsH, hsL, wkH, wkL, wvH, wvL, pk, pv);
        int tk = MROWS * NKV * (DH / 2);
        rope_split_kernel<<<(tk + 255) / 256, 256, 0, st1>>>(pk, cosb, sinb, ksH, ksL, NKV, 1.0f);
        splitvt_kernel<<<dim3(S_LEN / 64, NKV, BDIM), 256, 0, st1>>>(pv, vtH, vtL);
        cudaEventRecord(evKV, st1);
    }

    // ---- stream 2: wd split (needed only by out-proj) ----
    {
        int n4 = HQ * HQ / 4;
        split_kernel<<<(n4 + 255) / 256, 256, 0, st2>>>(wd, wdH, wdL, n4);
        cudaEventRecord(evWd, st2);
    }

    // ---- join: attention, then out-proj ----
    cudaStreamWaitEvent(0, evKV, 0);
    attn_mma_kernel<<<dim3(S_LEN / 64, NH, BDIM), 128, ATT_SMEM>>>(
        qsH, qsL, ksH, ksL, vtH, vtL, aoH, aoL);
    cudaStreamWaitEvent(0, evWd, 0);
    gemm3_kernel<<<dim3(HQ / GBN, MROWS / GBM), 256, GEMM_SMEM>>>(aoH, aoL, wdH, wdL, out, HQ, HQ);
}